// round 13
// baseline (speedup 1.0000x reference)
#include <cuda_runtime.h>
#include <cuda_bf16.h>
#include <math.h>
#include <stdint.h>

// ======================= scratch (device globals; no allocs) =======================
__device__ float g_a[33554432];   // 16*128*128*128
__device__ float g_b[8388608];    // 16*128*64*64
__device__ float g_c[4194304];    // 16*256*32*32 encoder chain
__device__ float g_t[4194304];    // resblock tmp
__device__ float g_z[2097152];
__device__ float g_zq[2097152];
__device__ float g_d[4194304];    // decoder chain
__device__ float g_scores[8388608];
__device__ int   g_idx[16384];
__device__ float g_cbnorm[512];
__device__ float g_hist[512];
__device__ float g_commit;
__device__ float g_bnscale[128];
__device__ float g_bnshift[128];
// tensor-core path buffers (two ping-pong NHWC pairs)
__device__ __nv_bfloat16 g_nh_hi[4734976];   // 16*34*34*256 padded NHWC (A)
__device__ __nv_bfloat16 g_nh_lo[4734976];
__device__ __nv_bfloat16 g_nh2_hi[4734976];  // (B)
__device__ __nv_bfloat16 g_nh2_lo[4734976];
__device__ __nv_bfloat16 g_w_hi[4718592];    // 8 sets * 9 taps * 256 oc * 256 ci
__device__ __nv_bfloat16 g_w_lo[4718592];
__device__ __nv_bfloat16 g_e_hi[17842176];   // 16*66*66*256 padded NHWC (deconv1 out)
__device__ __nv_bfloat16 g_e_lo[17842176];
__device__ __nv_bfloat16 g_wd1_hi[1048576];  // 4 phases * 4 taps * 256 oc * 256 ci
__device__ __nv_bfloat16 g_wd1_lo[1048576];
__device__ __nv_bfloat16 g_wd2_hi[524288];   // 4 phases * 4 taps * 128 oc * 256 ci
__device__ __nv_bfloat16 g_wd2_lo[524288];

// ======================= helpers =======================
__device__ __forceinline__ uint32_t smem_u32(const void* p) {
    return (uint32_t)__cvta_generic_to_shared(p);
}
__device__ __forceinline__ void cp16(uint32_t d, const void* s, bool pred) {
    int sz = pred ? 16 : 0;
    asm volatile("cp.async.ca.shared.global [%0], [%1], 16, %2;\n" :: "r"(d), "l"(s), "r"(sz));
}
__device__ __forceinline__ void cp4(uint32_t d, const void* s, bool pred) {
    int sz = pred ? 4 : 0;
    asm volatile("cp.async.ca.shared.global [%0], [%1], 4, %2;\n" :: "r"(d), "l"(s), "r"(sz));
}
__device__ __forceinline__ void cp_commit() { asm volatile("cp.async.commit_group;\n"); }
__device__ __forceinline__ void cp_wait1()  { asm volatile("cp.async.wait_group 1;\n"); }
__device__ __forceinline__ void cp_wait0()  { asm volatile("cp.async.wait_group 0;\n"); }

__device__ __forceinline__ void ldm4(uint32_t* r, uint32_t addr) {
    asm volatile("ldmatrix.sync.aligned.m8n8.x4.shared.b16 {%0,%1,%2,%3}, [%4];"
        : "=r"(r[0]), "=r"(r[1]), "=r"(r[2]), "=r"(r[3]) : "r"(addr));
}
__device__ __forceinline__ void mma16816(float* d, const uint32_t* a, uint32_t b0, uint32_t b1) {
    asm volatile("mma.sync.aligned.m16n8k16.row.col.f32.bf16.bf16.f32 "
        "{%0,%1,%2,%3}, {%4,%5,%6,%7}, {%8,%9}, {%0,%1,%2,%3};"
        : "+f"(d[0]), "+f"(d[1]), "+f"(d[2]), "+f"(d[3])
        : "r"(a[0]), "r"(a[1]), "r"(a[2]), "r"(a[3]), "r"(b0), "r"(b1));
}

// ======================= prep kernels =======================
__global__ void zero_halo2(__nv_bfloat16* __restrict__ hi, __nv_bfloat16* __restrict__ lo,
                           __nv_bfloat16* __restrict__ hi2, __nv_bfloat16* __restrict__ lo2)
{
    int b = blockIdx.x;               // 16*132
    int n = b / 132, i = b - n * 132;
    int y, x;
    if (i < 34)       { y = 0;  x = i; }
    else if (i < 68)  { y = 33; x = i - 34; }
    else if (i < 100) { y = i - 68 + 1;  x = 0; }
    else              { y = i - 100 + 1; x = 33; }
    size_t p = ((size_t)(n * 34 + y) * 34 + x) * 256 + threadIdx.x;
    __nv_bfloat16 z = __float2bfloat16(0.f);
    hi[p] = z; lo[p] = z; hi2[p] = z; lo2[p] = z;
}

__global__ void zero_halo66(__nv_bfloat16* __restrict__ hi, __nv_bfloat16* __restrict__ lo)
{
    int b = blockIdx.x;               // 16*260
    int n = b / 260, i = b - n * 260;
    int y, x;
    if (i < 66)        { y = 0;  x = i; }
    else if (i < 132)  { y = 65; x = i - 66; }
    else if (i < 196)  { y = i - 132 + 1; x = 0; }
    else               { y = i - 196 + 1; x = 65; }
    size_t p = ((size_t)(n * 66 + y) * 66 + x) * 256 + threadIdx.x;
    hi[p] = __float2bfloat16(0.f);
    lo[p] = __float2bfloat16(0.f);
}

// 8 sets: dec_rw1 (0-3), dec_rw2 (4-7)
__global__ void prep_wsplit(const float* __restrict__ d1, const float* __restrict__ d2,
                            __nv_bfloat16* __restrict__ hi, __nv_bfloat16* __restrict__ lo)
{
    int t = blockIdx.x * 256 + threadIdx.x;
    if (t >= 8 * 9 * 65536) return;
    int ci = t & 255;
    int oc = (t >> 8) & 255;
    int st = t >> 16;            // s*9 + tap
    int s = st / 9, tap = st - s * 9;
    const float* src = (s < 4) ? d1 : d2;
    int i = s & 3;
    float v = src[(((size_t)(i * 256 + oc) * 256 + ci) * 9) + tap];
    __nv_bfloat16 h = __float2bfloat16(v);
    hi[t] = h;
    lo[t] = __float2bfloat16(v - __bfloat162float(h));
}

// deconv weight split: phase/tap layout [ph*4+tt][oc][ci]
__global__ void prep_wsplit_dc(const float* __restrict__ w,
                               __nv_bfloat16* __restrict__ hi, __nv_bfloat16* __restrict__ lo,
                               int NOC)
{
    int t = blockIdx.x * 256 + threadIdx.x;
    if (t >= 16 * NOC * 256) return;
    int ci = t & 255;
    int rest = t >> 8;
    int oc = rest % NOC;
    int pt = rest / NOC;          // ph*4 + tt
    int ph = pt >> 2, tt = pt & 3;
    int a = ph >> 1, b = ph & 1;
    int kh = a + 2 * (tt >> 1);
    int kw = b + 2 * (tt & 1);
    float v = w[((size_t)oc * 256 + ci) * 16 + kh * 4 + kw];
    __nv_bfloat16 h = __float2bfloat16(v);
    hi[t] = h;
    lo[t] = __float2bfloat16(v - __bfloat162float(h));
}

// relu fp32->bf16 hi/lo split, NCHW -> 34x34 padded NHWC
__global__ __launch_bounds__(256)
void split_nhwc(const float* __restrict__ act, __nv_bfloat16* __restrict__ hi, __nv_bfloat16* __restrict__ lo)
{
    __shared__ float s[256][33];
    int b = blockIdx.x;          // 0..511
    int n = b >> 5, y = b & 31;
    const float* a = act + ((size_t)n * 262144) + y * 32;
    for (int idx = threadIdx.x; idx < 8192; idx += 256) {
        int ci = idx >> 5, x = idx & 31;
        s[ci][x] = a[(size_t)ci * 1024 + x];
    }
    __syncthreads();
    size_t pbase = ((size_t)(n * 34 + y + 1) * 34 + 1) * 256;
    for (int idx = threadIdx.x; idx < 8192; idx += 256) {
        int x = idx >> 8, ci = idx & 255;
        float v = fmaxf(s[ci][x], 0.f);
        __nv_bfloat16 h = __float2bfloat16(v);
        float rem = v - __bfloat162float(h);
        hi[pbase + (size_t)x * 256 + ci] = h;
        lo[pbase + (size_t)x * 256 + ci] = __float2bfloat16(rem);
    }
}

// ======================= mma.sync implicit-GEMM 3x3 conv (decoder resblocks) =======================
// EMIT: 0 = fp32 out only; 1 = relu'd hi/lo only (no fp32); 2 = fp32 + relu'd hi/lo; 3 = non-relu hi/lo only
static constexpr int GSM_TOTAL = 122880;

template<bool ADD, int EMIT>
__global__ __launch_bounds__(512, 1)
void gemm_conv3(const __nv_bfloat16* __restrict__ ahi, const __nv_bfloat16* __restrict__ alo,
                const __nv_bfloat16* __restrict__ bhi, const __nv_bfloat16* __restrict__ blo,
                const float* __restrict__ bias, float* __restrict__ out,
                __nv_bfloat16* __restrict__ ohi, __nv_bfloat16* __restrict__ olo)
{
    extern __shared__ char smem[];
    const uint32_t sbase = smem_u32(smem);
    const int tid = threadIdx.x;
    const int tile = blockIdx.x;       // 0..127
    const int n = tile >> 3;
    const int y0 = (tile & 7) << 2;

    const __nv_bfloat16* aHiN = ahi + (size_t)n * 295936;
    const __nv_bfloat16* aLoN = alo + (size_t)n * 295936;

    auto loadChunk = [&](int s, int st) {
        int tap = s >> 3;
        int c0 = (s & 7) << 5;
        int kh = tap / 3, kw = tap - kh * 3;
        uint32_t sb = sbase + (uint32_t)st * 61440u;
        {
            int r = tid >> 2, seg = tid & 3;
            int yy = y0 + (r >> 5) + kh, xx = (r & 31) + kw;
            size_t src = (size_t)(yy * 34 + xx) * 256 + c0 + seg * 8;
            uint32_t d = (uint32_t)(r * 80 + seg * 16);
            cp16(sb + d, aHiN + src, true);
            cp16(sb + 10240u + d, aLoN + src, true);
        }
        const __nv_bfloat16* bh = bhi + ((size_t)tap << 16) + c0;
        const __nv_bfloat16* bl = blo + ((size_t)tap << 16) + c0;
        for (int j = tid; j < 1024; j += 512) {
            int oc = j >> 2, seg = j & 3;
            size_t src = ((size_t)oc << 8) + seg * 8;
            uint32_t d = (uint32_t)(oc * 80 + seg * 16);
            cp16(sb + 20480u + d, bh + src, true);
            cp16(sb + 40960u + d, bl + src, true);
        }
        cp_commit();
    };

    const int w = tid >> 5, lane = tid & 31;
    const int wm = (w >> 2) << 5;
    const int wn = (w & 3) << 6;

    float acc[16][4];
#pragma unroll
    for (int i = 0; i < 16; i++)
#pragma unroll
        for (int j = 0; j < 4; j++) acc[i][j] = 0.f;

    const uint32_t aoff = (uint32_t)((wm + (lane & 15)) * 80 + ((lane >> 4) << 4));
    uint32_t boff[4];
    {
        int nloc = (lane & 7) + ((lane >> 4) & 1) * 8;
        int kb = ((lane >> 3) & 1) * 16;
#pragma unroll
        for (int j = 0; j < 4; j++)
            boff[j] = (uint32_t)((wn + j * 16 + nloc) * 80 + kb);
    }

    loadChunk(0, 0);
    loadChunk(1, 1);

    const int T = 72;
    for (int s = 0; s < T; s++) {
        int st = s & 1;
        if (s == T - 1) cp_wait0(); else cp_wait1();
        __syncthreads();
        uint32_t sb = sbase + (uint32_t)st * 61440u;
#pragma unroll
        for (int kk = 0; kk < 2; kk++) {
            uint32_t k32 = kk * 32;
            uint32_t ah[2][4], al[2][4], bb[16];
            ldm4(ah[0], sb + aoff + k32);
            ldm4(ah[1], sb + 1280u + aoff + k32);
            ldm4(al[0], sb + 10240u + aoff + k32);
            ldm4(al[1], sb + 11520u + aoff + k32);
#pragma unroll
            for (int j = 0; j < 4; j++) ldm4(&bb[4 * j], sb + 20480u + boff[j] + k32);
#pragma unroll
            for (int nt = 0; nt < 8; nt++)
#pragma unroll
                for (int mt = 0; mt < 2; mt++)
                    mma16816(acc[mt * 8 + nt], ah[mt], bb[2 * nt], bb[2 * nt + 1]);
#pragma unroll
            for (int nt = 0; nt < 8; nt++)
#pragma unroll
                for (int mt = 0; mt < 2; mt++)
                    mma16816(acc[mt * 8 + nt], al[mt], bb[2 * nt], bb[2 * nt + 1]);
#pragma unroll
            for (int j = 0; j < 4; j++) ldm4(&bb[4 * j], sb + 40960u + boff[j] + k32);
#pragma unroll
            for (int nt = 0; nt < 8; nt++)
#pragma unroll
                for (int mt = 0; mt < 2; mt++)
                    mma16816(acc[mt * 8 + nt], ah[mt], bb[2 * nt], bb[2 * nt + 1]);
        }
        __syncthreads();
        if (s + 2 < T) loadChunk(s + 2, st);
    }

    const int mrow = lane >> 2;
    const int ncol = (lane & 3) << 1;
    const size_t obase = (size_t)n * 262144 + (size_t)(y0 * 32);
#pragma unroll
    for (int mt = 0; mt < 2; mt++)
#pragma unroll
        for (int nt = 0; nt < 8; nt++) {
            const float* dd = acc[mt * 8 + nt];
            int oc = wn + nt * 8 + ncol;
            float b0 = __ldg(bias + oc), b1 = __ldg(bias + oc + 1);
#pragma unroll
            for (int hf = 0; hf < 2; hf++) {
                int m = wm + mt * 16 + mrow + hf * 8;
                float v0 = dd[hf * 2 + 0] + b0;
                float v1 = dd[hf * 2 + 1] + b1;
                size_t o0 = obase + (size_t)oc * 1024 + m;
                size_t o1 = o0 + 1024;
                if (ADD) { v0 += out[o0]; v1 += out[o1]; }
                if (EMIT == 0 || EMIT == 2) { out[o0] = v0; out[o1] = v1; }
                if (EMIT >= 1) {
                    float u0 = (EMIT == 3) ? v0 : fmaxf(v0, 0.f);
                    float u1 = (EMIT == 3) ? v1 : fmaxf(v1, 0.f);
                    int yy = y0 + (m >> 5), xx = m & 31;
                    size_t p = ((size_t)(n * 34 + yy + 1) * 34 + xx + 1) * 256 + oc;
                    __nv_bfloat16 h0 = __float2bfloat16(u0);
                    __nv_bfloat16 h1 = __float2bfloat16(u1);
                    ohi[p] = h0; ohi[p + 1] = h1;
                    olo[p]     = __float2bfloat16(u0 - __bfloat162float(h0));
                    olo[p + 1] = __float2bfloat16(u1 - __bfloat162float(h1));
                }
            }
        }
}

// ======================= mma.sync implicit-GEMM transposed conv (d1, d2) =======================
template<int WIDTH, int NOC, bool SPLIT_OUT>
__global__ __launch_bounds__(512, 1)
void gemm_deconv(const __nv_bfloat16* __restrict__ ahi, const __nv_bfloat16* __restrict__ alo,
                 const __nv_bfloat16* __restrict__ bhi, const __nv_bfloat16* __restrict__ blo,
                 const float* __restrict__ bias,
                 __nv_bfloat16* __restrict__ ohi, __nv_bfloat16* __restrict__ olo,
                 float* __restrict__ out)
{
    constexpr int MT = 4 * WIDTH;
    constexpr int PW = WIDTH + 2;
    constexpr int WN_WARPS = NOC / 64;
    constexpr uint32_t A_LO = MT * 80;
    constexpr uint32_t B_HI = 2 * MT * 80;
    constexpr uint32_t B_LO = B_HI + NOC * 80;
    constexpr int YTILES = WIDTH / 4;

    extern __shared__ char smem[];
    const uint32_t sbase = smem_u32(smem);
    const int tid = threadIdx.x;
    const int n = blockIdx.x / YTILES;
    const int y0 = (blockIdx.x % YTILES) * 4;
    const int ph = blockIdx.y;
    const int pa = ph >> 1, pb = ph & 1;

    const size_t imgStride = (size_t)PW * PW * 256;
    const __nv_bfloat16* aHiN = ahi + (size_t)n * imgStride;
    const __nv_bfloat16* aLoN = alo + (size_t)n * imgStride;

    auto loadChunk = [&](int s, int st) {
        int tt = s >> 3;
        int c0 = (s & 7) << 5;
        int dy = pa - 1 + (tt >> 1);
        int dx = pb - 1 + (tt & 1);
        uint32_t sb = sbase + (uint32_t)st * 61440u;
        for (int j = tid; j < MT * 4; j += 512) {
            int r = j >> 2, seg = j & 3;
            int yy = y0 + r / WIDTH + dy + 1;
            int xx = r % WIDTH + dx + 1;
            size_t src = (size_t)(yy * PW + xx) * 256 + c0 + seg * 8;
            uint32_t d = (uint32_t)(r * 80 + seg * 16);
            cp16(sb + d, aHiN + src, true);
            cp16(sb + A_LO + d, aLoN + src, true);
        }
        const __nv_bfloat16* bh = bhi + ((size_t)(ph * 4 + tt) * NOC << 8) + c0;
        const __nv_bfloat16* bl = blo + ((size_t)(ph * 4 + tt) * NOC << 8) + c0;
        for (int j = tid; j < NOC * 4; j += 512) {
            int oc = j >> 2, seg = j & 3;
            size_t src = ((size_t)oc << 8) + seg * 8;
            uint32_t d = (uint32_t)(oc * 80 + seg * 16);
            cp16(sb + B_HI + d, bh + src, true);
            cp16(sb + B_LO + d, bl + src, true);
        }
        cp_commit();
    };

    const int w = tid >> 5, lane = tid & 31;
    const int wm = (w / WN_WARPS) << 5;
    const int wn = (w % WN_WARPS) << 6;

    float acc[16][4];
#pragma unroll
    for (int i = 0; i < 16; i++)
#pragma unroll
        for (int j = 0; j < 4; j++) acc[i][j] = 0.f;

    const uint32_t aoff = (uint32_t)((wm + (lane & 15)) * 80 + ((lane >> 4) << 4));
    uint32_t boff[4];
    {
        int nloc = (lane & 7) + ((lane >> 4) & 1) * 8;
        int kb = ((lane >> 3) & 1) * 16;
#pragma unroll
        for (int j = 0; j < 4; j++)
            boff[j] = (uint32_t)((wn + j * 16 + nloc) * 80 + kb);
    }

    loadChunk(0, 0);
    loadChunk(1, 1);

    const int T = 32;
    for (int s = 0; s < T; s++) {
        int st = s & 1;
        if (s == T - 1) cp_wait0(); else cp_wait1();
        __syncthreads();
        uint32_t sb = sbase + (uint32_t)st * 61440u;
#pragma unroll
        for (int kk = 0; kk < 2; kk++) {
            uint32_t k32 = kk * 32;
            uint32_t ah[2][4], al[2][4], bb[16];
            ldm4(ah[0], sb + aoff + k32);
            ldm4(ah[1], sb + 1280u + aoff + k32);
            ldm4(al[0], sb + A_LO + aoff + k32);
            ldm4(al[1], sb + A_LO + 1280u + aoff + k32);
#pragma unroll
            for (int j = 0; j < 4; j++) ldm4(&bb[4 * j], sb + B_HI + boff[j] + k32);
#pragma unroll
            for (int nt = 0; nt < 8; nt++)
#pragma unroll
                for (int mt = 0; mt < 2; mt++)
                    mma16816(acc[mt * 8 + nt], ah[mt], bb[2 * nt], bb[2 * nt + 1]);
#pragma unroll
            for (int nt = 0; nt < 8; nt++)
#pragma unroll
                for (int mt = 0; mt < 2; mt++)
                    mma16816(acc[mt * 8 + nt], al[mt], bb[2 * nt], bb[2 * nt + 1]);
#pragma unroll
            for (int j = 0; j < 4; j++) ldm4(&bb[4 * j], sb + B_LO + boff[j] + k32);
#pragma unroll
            for (int nt = 0; nt < 8; nt++)
#pragma unroll
                for (int mt = 0; mt < 2; mt++)
                    mma16816(acc[mt * 8 + nt], ah[mt], bb[2 * nt], bb[2 * nt + 1]);
        }
        __syncthreads();
        if (s + 2 < T) loadChunk(s + 2, st);
    }

    const int mrow = lane >> 2;
    const int ncol = (lane & 3) << 1;
#pragma unroll
    for (int mt = 0; mt < 2; mt++)
#pragma unroll
        for (int nt = 0; nt < 8; nt++) {
            const float* dd = acc[mt * 8 + nt];
            int oc = wn + nt * 8 + ncol;
            float b0 = __ldg(bias + oc), b1 = __ldg(bias + oc + 1);
#pragma unroll
            for (int half = 0; half < 2; half++) {
                int m = wm + mt * 16 + mrow + half * 8;
                int iy = y0 + m / WIDTH, jx = m % WIDTH;
                int oy = 2 * iy + pa, ox = 2 * jx + pb;
                float v0 = fmaxf(dd[half * 2 + 0] + b0, 0.f);
                float v1 = fmaxf(dd[half * 2 + 1] + b1, 0.f);
                if (SPLIT_OUT) {
                    size_t p = ((size_t)(n * 66 + oy + 1) * 66 + ox + 1) * 256 + oc;
                    __nv_bfloat16 h0 = __float2bfloat16(v0);
                    __nv_bfloat16 h1 = __float2bfloat16(v1);
                    ohi[p] = h0; ohi[p + 1] = h1;
                    olo[p]     = __float2bfloat16(v0 - __bfloat162float(h0));
                    olo[p + 1] = __float2bfloat16(v1 - __bfloat162float(h1));
                } else {
                    size_t o = (((size_t)n * NOC + oc) * (2 * WIDTH) + oy) * (2 * WIDTH) + ox;
                    out[o] = v0;
                    out[o + (size_t)(2 * WIDTH) * (2 * WIDTH)] = v1;
                }
            }
        }
}

// ======================= R2 pipelined 3x3 conv (encoder resblocks, exact fp32) =======================
template<bool RELU_IN, bool ADD>
__global__ __launch_bounds__(64)
void conv3_pipe(const float* __restrict__ in, const float* __restrict__ wgt,
                const float* __restrict__ bias, float* __restrict__ out,
                int Cin, int Cout)
{
    constexpr int CI = 4;
    __shared__ __align__(16) float s_in[2][CI][18][36];
    __shared__ __align__(16) float s_w[2][8][CI][12];

    const int tY  = blockIdx.x;
    const int oc0 = blockIdx.y * 8;
    const int n   = blockIdx.z;
    const int tid = threadIdx.x;
    const int ty  = tid >> 3, tx = tid & 7;
    const int iR0 = tY * 16 - 1;

    const float* inN = in + (size_t)n * Cin * 1024;
    const int nCh = Cin / CI;

    for (int i = tid; i < 2 * CI * 18; i += 64) {
        int st = i / (CI * 18);
        int r  = i % (CI * 18);
        int ci = r / 18, rr = r % 18;
        float4 z4 = {0.f, 0.f, 0.f, 0.f};
        *(float4*)&s_in[st][ci][rr][32] = z4;
    }

    auto prefetch = [&](int ch, int st) {
        const float* gi = inN + (size_t)ch * CI * 1024;
        for (int k = tid; k < CI * 18 * 8; k += 64) {
            int ci = k / 144;
            int rem = k - ci * 144;
            int r = rem >> 3, j = rem & 7;
            int gr = iR0 + r;
            bool p = (unsigned)gr < 32u;
            int grc = p ? gr : 0;
            cp16(smem_u32(&s_in[st][ci][r][4 * j]), gi + ci * 1024 + grc * 32 + 4 * j, p);
        }
        if (tid < 32) {
            int oc = tid >> 2, ci = tid & 3;
            const float* gw = wgt + ((size_t)(oc0 + oc) * Cin + ch * CI + ci) * 9;
            uint32_t d = smem_u32(&s_w[st][oc][ci][0]);
#pragma unroll
            for (int w = 0; w < 9; w++) cp4(d + 4 * w, gw + w, true);
        }
    };

    float acc[8][2][4];
#pragma unroll
    for (int o = 0; o < 8; o++)
#pragma unroll
        for (int r = 0; r < 2; r++)
#pragma unroll
            for (int c = 0; c < 4; c++) acc[o][r][c] = 0.f;

    prefetch(0, 0);
    cp_commit();

    const int lidx = (tx == 0) ? 34 : (4 * tx - 1);

    for (int ch = 0; ch < nCh; ch++) {
        int st = ch & 1;
        if (ch + 1 < nCh) { prefetch(ch + 1, st ^ 1); cp_commit(); cp_wait1(); }
        else              { cp_wait0(); }
        __syncthreads();
#pragma unroll 1
        for (int ci = 0; ci < CI; ci++) {
            float rin[4][6];
#pragma unroll
            for (int rr = 0; rr < 4; rr++) {
                int r = 2 * ty + rr;
                float l = s_in[st][ci][r][lidx];
                float4 m = *(const float4*)&s_in[st][ci][r][4 * tx];
                float rg = s_in[st][ci][r][4 * tx + 4];
                rin[rr][0] = l; rin[rr][1] = m.x; rin[rr][2] = m.y;
                rin[rr][3] = m.z; rin[rr][4] = m.w; rin[rr][5] = rg;
                if (RELU_IN) {
#pragma unroll
                    for (int u = 0; u < 6; u++) rin[rr][u] = fmaxf(rin[rr][u], 0.f);
                }
            }
#pragma unroll
            for (int oc = 0; oc < 8; oc++) {
                float wk[9];
                float4 w0 = *(const float4*)&s_w[st][oc][ci][0];
                float4 w1 = *(const float4*)&s_w[st][oc][ci][4];
                wk[0] = w0.x; wk[1] = w0.y; wk[2] = w0.z; wk[3] = w0.w;
                wk[4] = w1.x; wk[5] = w1.y; wk[6] = w1.z; wk[7] = w1.w;
                wk[8] = s_w[st][oc][ci][8];
#pragma unroll
                for (int ry = 0; ry < 2; ry++)
#pragma unroll
                    for (int cx = 0; cx < 4; cx++) {
                        float a = acc[oc][ry][cx];
#pragma unroll
                        for (int kh = 0; kh < 3; kh++)
#pragma unroll
                            for (int kw = 0; kw < 3; kw++)
                                a = fmaf(rin[ry + kh][cx + kw], wk[kh * 3 + kw], a);
                        acc[oc][ry][cx] = a;
                    }
            }
        }
        __syncthreads();
    }

#pragma unroll
    for (int oc = 0; oc < 8; oc++) {
        int ocg = oc0 + oc;
        float bv = bias[ocg];
#pragma unroll
        for (int ry = 0; ry < 2; ry++) {
            int R = 16 * tY + 2 * ty + ry;
            size_t o = (((size_t)n * Cout + ocg) * 32 + R) * 32 + 4 * tx;
            float4 v;
            v.x = acc[oc][ry][0] + bv; v.y = acc[oc][ry][1] + bv;
            v.z = acc[oc][ry][2] + bv; v.w = acc[oc][ry][3] + bv;
            if (ADD) {
                float4 p = *(const float4*)&out[o];
                v.x += p.x; v.y += p.y; v.z += p.z; v.w += p.w;
            }
            *(float4*)&out[o] = v;
        }
    }
}

// ======================= R2 pipelined 4x4 stride-2 conv (e2, e3) =======================
__global__ __launch_bounds__(64)
void conv4s2_pipe(const float* __restrict__ in, const float* __restrict__ wgt,
                  const float* __restrict__ bias, float* __restrict__ out,
                  int Cin, int Cout, int Hin, int Win, int tilesX)
{
    constexpr int CI = 2;
    __shared__ __align__(16) float s_in[2][CI][34][68];
    __shared__ __align__(16) float s_w[2][4][CI][16];

    const int tY   = blockIdx.x / tilesX;
    const int tX   = blockIdx.x - tY * tilesX;
    const int oc0  = blockIdx.y * 4;
    const int n    = blockIdx.z;
    const int tid  = threadIdx.x;
    const int ty   = tid >> 3, tx = tid & 7;
    const int iR0  = tY * 32 - 1;
    const int gc0  = tX * 64;
    const int Hout = Hin >> 1, Wout = Win >> 1;

    const float* inN = in + (size_t)n * Cin * Hin * Win;
    const int nCh = Cin / CI;

    auto prefetch = [&](int ch, int st) {
        const float* gi = inN + (size_t)ch * CI * Hin * Win;
        for (int k = tid; k < CI * 34 * 16; k += 64) {
            int ci = k / 544;
            int rem = k - ci * 544;
            int r = rem >> 4, j = rem & 15;
            int gr = iR0 + r;
            bool p = (unsigned)gr < (unsigned)Hin;
            int grc = p ? gr : 0;
            cp16(smem_u32(&s_in[st][ci][r][4 * j]), gi + (size_t)ci * Hin * Win + (size_t)grc * Win + gc0 + 4 * j, p);
        }
        for (int k = tid; k < CI * 34; k += 64) {
            int ci = k / 34, r = k - ci * 34;
            int gr = iR0 + r;
            bool rok = (unsigned)gr < (unsigned)Hin;
            int grc = rok ? gr : 0;
            const float* rowp = gi + (size_t)ci * Hin * Win + (size_t)grc * Win;
            cp4(smem_u32(&s_in[st][ci][r][66]), rowp + gc0 - 1, rok && gc0 > 0);
            cp4(smem_u32(&s_in[st][ci][r][64]), rowp + gc0 + 64, rok && (gc0 + 64 < Win));
        }
        if (tid < 4 * CI * 4) {
            int pair = tid >> 2, seg = tid & 3;
            int oc = pair / CI, ci = pair - oc * CI;
            const float* gw = wgt + ((size_t)(oc0 + oc) * Cin + ch * CI + ci) * 16 + seg * 4;
            cp16(smem_u32(&s_w[st][oc][ci][seg * 4]), gw, true);
        }
    };

    float acc[4][2][4];
#pragma unroll
    for (int o = 0; o < 4; o++)
#pragma unroll
        for (int r = 0; r < 2; r++)
#pragma unroll
            for (int c = 0; c < 4; c++) acc[o][r][c] = 0.f;

    prefetch(0, 0);
    cp_commit();

    const int lidx = (tx == 0) ? 66 : (8 * tx - 1);

    for (int ch = 0; ch < nCh; ch++) {
        int st = ch & 1;
        if (ch + 1 < nCh) { prefetch(ch + 1, st ^ 1); cp_commit(); cp_wait1(); }
        else              { cp_wait0(); }
        __syncthreads();
#pragma unroll 1
        for (int ci = 0; ci < CI; ci++) {
            float rin[6][10];
#pragma unroll
            for (int rr = 0; rr < 6; rr++) {
                int r = 4 * ty + rr;
                rin[rr][0] = s_in[st][ci][r][lidx];
                float4 m0 = *(const float4*)&s_in[st][ci][r][8 * tx];
                float4 m1 = *(const float4*)&s_in[st][ci][r][8 * tx + 4];
                rin[rr][1] = m0.x; rin[rr][2] = m0.y; rin[rr][3] = m0.z; rin[rr][4] = m0.w;
                rin[rr][5] = m1.x; rin[rr][6] = m1.y; rin[rr][7] = m1.z; rin[rr][8] = m1.w;
                rin[rr][9] = s_in[st][ci][r][8 * tx + 8];
            }
#pragma unroll
            for (int oc = 0; oc < 4; oc++) {
                float wk[16];
#pragma unroll
                for (int s4 = 0; s4 < 4; s4++) {
                    float4 w = *(const float4*)&s_w[st][oc][ci][4 * s4];
                    wk[4 * s4] = w.x; wk[4 * s4 + 1] = w.y; wk[4 * s4 + 2] = w.z; wk[4 * s4 + 3] = w.w;
                }
#pragma unroll
                for (int ry = 0; ry < 2; ry++)
#pragma unroll
                    for (int cx = 0; cx < 4; cx++) {
                        float a = acc[oc][ry][cx];
#pragma unroll
                        for (int kh = 0; kh < 4; kh++)
#pragma unroll
                            for (int kw = 0; kw < 4; kw++)
                                a = fmaf(rin[2 * ry + kh][2 * cx + kw], wk[kh * 4 + kw], a);
                        acc[oc][ry][cx] = a;
                    }
            }
        }
        __syncthreads();
    }

#pragma unroll
    for (int oc = 0; oc < 4; oc++) {
        int ocg = oc0 + oc;
        float bv = bias[ocg];
#pragma unroll
        for (int ry = 0; ry < 2; ry++) {
            int R = 16 * tY + 2 * ty + ry;
            int C = 32 * tX + 4 * tx;
            size_t o = (((size_t)n * Cout + ocg) * Hout + R) * Wout + C;
            float4 v;
            v.x = fmaxf(acc[oc][ry][0] + bv, 0.f);
            v.y = fmaxf(acc[oc][ry][1] + bv, 0.f);
            v.z = fmaxf(acc[oc][ry][2] + bv, 0.f);
            v.w = fmaxf(acc[oc][ry][3] + bv, 0.f);
            *(float4*)&out[o] = v;
        }
    }
}

// ======================= R2 pipelined transposed conv (d3 only) =======================
template<bool RELU_OUT>
__global__ __launch_bounds__(128)
void deconv_pipe(const float* __restrict__ in, const float* __restrict__ wgt,
                 const float* __restrict__ bias, float* __restrict__ out,
                 int Cin, int Cout, int Hin, int Win, int tilesX)
{
    constexpr int CI = 4;
    __shared__ __align__(16) float s_in[2][CI][18][36];
    __shared__ __align__(16) float s_w[2][4][CI][16];

    const int tY   = blockIdx.x / tilesX;
    const int tX   = blockIdx.x - tY * tilesX;
    const int oc0  = blockIdx.y * 4;
    const int n    = blockIdx.z;
    const int tid  = threadIdx.x;
    const int ty   = tid >> 3, tx = tid & 7;
    const int iR0  = tY * 16;
    const int iC0  = tX * 32;
    const int Hout = 2 * Hin, Wout = 2 * Win;

    const float* inN = in + (size_t)n * Cin * Hin * Win;
    const int nCh = Cin / CI;

    auto prefetch = [&](int ch, int st) {
        const float* gi = inN + (size_t)ch * CI * Hin * Win;
        for (int k = tid; k < CI * 18 * 8; k += 128) {
            int ci = k / 144;
            int rem = k - ci * 144;
            int r = rem >> 3, j = rem & 7;
            int gr = iR0 - 1 + r;
            bool p = (unsigned)gr < (unsigned)Hin;
            int grc = p ? gr : 0;
            cp16(smem_u32(&s_in[st][ci][r][4 * j]), gi + (size_t)ci * Hin * Win + (size_t)grc * Win + iC0 + 4 * j, p);
        }
        for (int k = tid; k < CI * 18; k += 128) {
            int ci = k / 18, r = k - ci * 18;
            int gr = iR0 - 1 + r;
            bool rok = (unsigned)gr < (unsigned)Hin;
            int grc = rok ? gr : 0;
            const float* rowp = gi + (size_t)ci * Hin * Win + (size_t)grc * Win;
            cp4(smem_u32(&s_in[st][ci][r][34]), rowp + iC0 - 1, rok && iC0 > 0);
            cp4(smem_u32(&s_in[st][ci][r][32]), rowp + iC0 + 32, rok && (iC0 + 32 < Win));
        }
        if (tid < 4 * CI * 4) {
            int pair = tid >> 2, seg = tid & 3;
            int oc = pair / CI, ci = pair - oc * CI;
            bool p = (oc0 + oc) < Cout;
            const float* gw = wgt + ((size_t)(oc0 + oc) * Cin + ch * CI + ci) * 16 + seg * 4;
            cp16(smem_u32(&s_w[st][oc][ci][seg * 4]), p ? gw : wgt, p);
        }
    };

    float acc[4][2][8];
#pragma unroll
    for (int o = 0; o < 4; o++)
#pragma unroll
        for (int a = 0; a < 2; a++)
#pragma unroll
            for (int u = 0; u < 8; u++) acc[o][a][u] = 0.f;

    prefetch(0, 0);
    cp_commit();

    const int lidx = (tx == 0) ? 34 : (4 * tx - 1);

    for (int ch = 0; ch < nCh; ch++) {
        int st = ch & 1;
        if (ch + 1 < nCh) { prefetch(ch + 1, st ^ 1); cp_commit(); cp_wait1(); }
        else              { cp_wait0(); }
        __syncthreads();
#pragma unroll 1
        for (int ci = 0; ci < CI; ci++) {
            float rin[3][6];
#pragma unroll
            for (int r = 0; r < 3; r++) {
                int rr = ty + r;
                rin[r][0] = s_in[st][ci][rr][lidx];
                float4 m = *(const float4*)&s_in[st][ci][rr][4 * tx];
                rin[r][1] = m.x; rin[r][2] = m.y; rin[r][3] = m.z; rin[r][4] = m.w;
                rin[r][5] = s_in[st][ci][rr][4 * tx + 4];
            }
#pragma unroll
            for (int oc = 0; oc < 4; oc++) {
                float wk[16];
#pragma unroll
                for (int s4 = 0; s4 < 4; s4++) {
                    float4 w = *(const float4*)&s_w[st][oc][ci][4 * s4];
                    wk[4 * s4] = w.x; wk[4 * s4 + 1] = w.y; wk[4 * s4 + 2] = w.z; wk[4 * s4 + 3] = w.w;
                }
#pragma unroll
                for (int jj = 0; jj < 4; jj++) {
#pragma unroll
                    for (int a = 0; a < 2; a++) {
                        const int rlo = a, rhi = a + 1;
                        const int khlo = a, khhi = a + 2;
#pragma unroll
                        for (int b = 0; b < 2; b++) {
                            const int clo = jj + b, chi = jj + 1 + b;
                            const int kwlo = b, kwhi = b + 2;
                            float v = acc[oc][a][2 * jj + b];
                            v = fmaf(rin[rlo][clo], wk[khlo * 4 + kwlo], v);
                            v = fmaf(rin[rlo][chi], wk[khlo * 4 + kwhi], v);
                            v = fmaf(rin[rhi][clo], wk[khhi * 4 + kwlo], v);
                            v = fmaf(rin[rhi][chi], wk[khhi * 4 + kwhi], v);
                            acc[oc][a][2 * jj + b] = v;
                        }
                    }
                }
            }
        }
        __syncthreads();
    }

#pragma unroll
    for (int oc = 0; oc < 4; oc++) {
        int ocg = oc0 + oc;
        if (ocg >= Cout) break;
        float bv = bias[ocg];
#pragma unroll
        for (int a = 0; a < 2; a++) {
            int p = 2 * (iR0 + ty) + a;
            int q = 2 * (iC0 + 4 * tx);
            size_t o = (((size_t)n * Cout + ocg) * Hout + p) * Wout + q;
            float4 v0, v1;
            v0.x = acc[oc][a][0] + bv; v0.y = acc[oc][a][1] + bv;
            v0.z = acc[oc][a][2] + bv; v0.w = acc[oc][a][3] + bv;
            v1.x = acc[oc][a][4] + bv; v1.y = acc[oc][a][5] + bv;
            v1.z = acc[oc][a][6] + bv; v1.w = acc[oc][a][7] + bv;
            if (RELU_OUT) {
                v0.x = fmaxf(v0.x, 0.f); v0.y = fmaxf(v0.y, 0.f);
                v0.z = fmaxf(v0.z, 0.f); v0.w = fmaxf(v0.w, 0.f);
                v1.x = fmaxf(v1.x, 0.f); v1.y = fmaxf(v1.y, 0.f);
                v1.z = fmaxf(v1.z, 0.f); v1.w = fmaxf(v1.w, 0.f);
            }
            *(float4*)&out[o] = v0;
            *(float4*)&out[o + 4] = v1;
        }
    }
}

// ======================= generic direct conv (e1 and 1x1 convs) =======================
template<int K, int S, int CI, int OCPT, bool RELU_IN, bool RELU_OUT, bool ADD, bool BN>
__global__ __launch_bounds__(128)
void conv_generic(const float* __restrict__ in, const float* __restrict__ wgt,
                  const float* __restrict__ bias, float* __restrict__ out,
                  int Cin, int Cout, int Hin, int Win, int Hout, int Wout, int tilesX,
                  const float* __restrict__ bnsc, const float* __restrict__ bnsh)
{
    constexpr int P   = (K == 1) ? 0 : 1;
    constexpr int IT  = 31 * S + K;
    constexpr int ITS = IT + 1;
    constexpr int KK  = K * K;
    constexpr int RR  = S + K;
    constexpr int CC  = 3 * S + K;

    __shared__ float s_in[CI][IT][ITS];
    __shared__ float s_w[OCPT][CI][KK];

    const int n   = blockIdx.z;
    const int oc0 = blockIdx.y * OCPT;
    const int tY  = blockIdx.x / tilesX;
    const int tX  = blockIdx.x - tY * tilesX;
    const int oR0 = tY * 32, oC0 = tX * 32;
    const int iR0 = oR0 * S - P, iC0 = oC0 * S - P;
    const int tid = threadIdx.x;
    const int ty  = tid >> 3, tx = tid & 7;

    float acc[OCPT][2][4];
#pragma unroll
    for (int o = 0; o < OCPT; o++)
#pragma unroll
        for (int r = 0; r < 2; r++)
#pragma unroll
            for (int c = 0; c < 4; c++) acc[o][r][c] = 0.f;

    const float* inN = in + (size_t)n * Cin * Hin * Win;

    for (int ic0 = 0; ic0 < Cin; ic0 += CI) {
        __syncthreads();
        for (int idx = tid; idx < CI * IT * IT; idx += 128) {
            int ci  = idx / (IT * IT);
            int rem = idx - ci * (IT * IT);
            int r   = rem / IT;
            int c   = rem - r * IT;
            int gr = iR0 + r, gc = iC0 + c;
            float v = 0.f;
            if ((unsigned)gr < (unsigned)Hin && (unsigned)gc < (unsigned)Win) {
                v = inN[((size_t)(ic0 + ci) * Hin + gr) * Win + gc];
                if (RELU_IN) v = fmaxf(v, 0.f);
            }
            s_in[ci][r][c] = v;
        }
        for (int idx = tid; idx < OCPT * CI * KK; idx += 128) {
            int oc  = idx / (CI * KK);
            int rem = idx - oc * (CI * KK);
            int ci  = rem / KK;
            int k   = rem - ci * KK;
            float wv = 0.f;
            if (oc0 + oc < Cout) wv = wgt[((size_t)(oc0 + oc) * Cin + ic0 + ci) * KK + k];
            s_w[oc][ci][k] = wv;
        }
        __syncthreads();
#pragma unroll 1
        for (int ci = 0; ci < CI; ci++) {
            float rin[RR][CC];
#pragma unroll
            for (int r = 0; r < RR; r++)
#pragma unroll
                for (int c = 0; c < CC; c++)
                    rin[r][c] = s_in[ci][2 * ty * S + r][4 * tx * S + c];
#pragma unroll
            for (int oc = 0; oc < OCPT; oc++) {
                float wk[KK];
#pragma unroll
                for (int k = 0; k < KK; k++) wk[k] = s_w[oc][ci][k];
#pragma unroll
                for (int ry = 0; ry < 2; ry++)
#pragma unroll
                    for (int cx = 0; cx < 4; cx++) {
                        float a = acc[oc][ry][cx];
#pragma unroll
                        for (int kh = 0; kh < K; kh++)
#pragma unroll
                            for (int kw = 0; kw < K; kw++)
                                a = fmaf(rin[ry * S + kh][cx * S + kw], wk[kh * K + kw], a);
                        acc[oc][ry][cx] = a;
                    }
            }
        }
    }
#pragma unroll
    for (int oc = 0; oc < OCPT; oc++) {
        int ocg = oc0 + oc;
        if (ocg >= Cout) break;
        float bv = bias[ocg];
        float sc = 1.f, sh = 0.f;
        if (BN) { sc = bnsc[ocg]; sh = bnsh[ocg]; }
#pragma unroll
        for (int ry = 0; ry < 2; ry++) {
            int r = oR0 + 2 * ty + ry;
#pragma unroll
            for (int cx = 0; cx < 4; cx++) {
                int c = oC0 + 4 * tx + cx;
                size_t o = (((size_t)n * Cout + ocg) * Hout + r) * Wout + c;
                float v = acc[oc][ry][cx] + bv;
                if (BN) v = v * sc + sh;
                if (ADD) v += out[o];
                if (RELU_OUT) v = fmaxf(v, 0.f);
                out[o] = v;
            }
        }
    }
}

// ======================= BN fold =======================
__global__ void bn_prep(const float* __restrict__ g, const float* __restrict__ b,
                        const float* __restrict__ m, const float* __restrict__ v,
                        float* __restrict__ sc, float* __restrict__ sh)
{
    int c = threadIdx.x;
    if (c < 128) {
        float s = g[c] / sqrtf(v[c] + 1e-5f);
        sc[c] = s;
        sh[c] = b[c] - m[c] * s;
    }
}

// ======================= VQ =======================
__global__ void vq_cbnorm(const float* __restrict__ cb, float* __restrict__ cbn)
{
    int k = blockIdx.x * blockDim.x + threadIdx.x;
    if (k >= 512) return;
    float s = 0.f;
    for (int c = 0; c < 128; c++) { float v = cb[k * 128 + c]; s = fmaf(v, v, s); }
    cbn[k] = s;
}

__global__ void vq_init(float* __restrict__ hist, float* __restrict__ commit)
{
    int t = threadIdx.x;
    if (t < 512) hist[t] = 0.f;
    if (t == 0) *commit = 0.f;
}

__global__ __launch_bounds__(256)
void vq_gemm(const float* __restrict__ z, const float* __restrict__ cb, float* __restrict__ scores)
{
    __shared__ float sA[16][128];
    __shared__ float sB[16][65];
    const int mt = blockIdx.x;
    const int kt = blockIdx.y;
    const int n  = mt >> 3;
    const int s0 = (mt & 7) << 7;
    const int m0 = mt << 7;
    const int k0 = kt << 6;
    const int tid = threadIdx.x;
    const int tr = tid >> 4, tc = tid & 15;

    float acc[8][4];
#pragma unroll
    for (int i = 0; i < 8; i++)
#pragma unroll
        for (int j = 0; j < 4; j++) acc[i][j] = 0.f;

    const float* zb = z + (size_t)n * 131072 + s0;

    for (int c0 = 0; c0 < 128; c0 += 16) {
        __syncthreads();
#pragma unroll
        for (int i = 0; i < 8; i++) {
            int idx = tid + i * 256;
            int cl = idx >> 7, ml = idx & 127;
            sA[cl][ml] = zb[(size_t)(c0 + cl) * 1024 + ml];
        }
#pragma unroll
        for (int i = 0; i < 4; i++) {
            int idx = tid + i * 256;
            int kl = idx >> 4, cl = idx & 15;
            sB[cl][kl] = cb[(size_t)(k0 + kl) * 128 + c0 + cl];
        }
        __syncthreads();
#pragma unroll
        for (int kk = 0; kk < 16; kk++) {
            float a[8], b[4];
#pragma unroll
            for (int i = 0; i < 8; i++) a[i] = sA[kk][i * 16 + tr];
#pragma unroll
            for (int j = 0; j < 4; j++) b[j] = sB[kk][j * 16 + tc];
#pragma unroll
            for (int i = 0; i < 8; i++)
#pragma unroll
                for (int j = 0; j < 4; j++)
                    acc[i][j] = fmaf(a[i], b[j], acc[i][j]);
        }
    }
#pragma unroll
    for (int i = 0; i < 8; i++)
#pragma unroll
        for (int j = 0; j < 4; j++)
            scores[(size_t)(m0 + i * 16 + tr) * 512 + k0 + j * 16 + tc] = acc[i][j];
}

__global__ __launch_bounds__(256)
void vq_argmin(const float* __restrict__ scores, const float* __restrict__ cbn, int* __restrict__ idxo)
{
    int gw = (blockIdx.x * blockDim.x + threadIdx.x) >> 5;
    int lane = threadIdx.x & 31;
    if (gw >= 16384) return;
    const float* row = scores + (size_t)gw * 512;
    float best = 3.4e38f;
    int bi = 0;
    for (int k = lane; k < 512; k += 32) {
        float v = cbn[k] - 2.f * row[k];
        if (v < best) { best = v; bi = k; }
    }
#pragma unroll
    for (int off = 16; off; off >>= 1) {
        float ob = __shfl_down_sync(0xFFFFFFFFu, best, off);
        int   oi = __shfl_down_sync(0xFFFFFFFFu, bi, off);
        if (ob < best || (ob == best && oi < bi)) { best = ob; bi = oi; }
    }
    if (lane == 0) idxo[gw] = bi;
}

__global__ __launch_bounds__(256)
void vq_gather(const float* __restrict__ z, const float* __restrict__ cb,
               const int* __restrict__ idx, float* __restrict__ zq,
               float* __restrict__ hist, float* __restrict__ commit)
{
    int m = blockIdx.x * 256 + threadIdx.x;
    int n = m >> 10, s = m & 1023;
    int k = idx[m];
    atomicAdd(&hist[k], 1.0f);
    const float* zb  = z  + (size_t)n * 131072 + s;
    float*       qb  = zq + (size_t)n * 131072 + s;
    const float* cbk = cb + (size_t)k * 128;
    float sum = 0.f;
    for (int c = 0; c < 128; c++) {
        float q  = __ldg(&cbk[c]);
        float zv = zb[(size_t)c * 1024];
        qb[(size_t)c * 1024] = q;
        float d = zv - q;
        sum = fmaf(d, d, sum);
    }
    __shared__ float red[256];
    red[threadIdx.x] = sum;
    __syncthreads();
    for (int o = 128; o; o >>= 1) {
        if (threadIdx.x < o) red[threadIdx.x] += red[threadIdx.x + o];
        __syncthreads();
    }
    if (threadIdx.x == 0) atomicAdd(commit, red[0]);
}

__global__ void vq_finalize(const float* __restrict__ hist, const float* __restrict__ commit,
                            float* __restrict__ out2)
{
    __shared__ float red[512];
    int k = threadIdx.x;
    float p = hist[k] * (1.0f / 16384.0f);
    red[k] = p * logf(p + 1e-10f);
    __syncthreads();
    for (int o = 256; o; o >>= 1) {
        if (k < o) red[k] += red[k + o];
        __syncthreads();
    }
    if (k == 0) {
        out2[0] = 0.25f * (*commit) / (16384.0f * 128.0f);
        out2[1] = expf(-red[0]);
    }
}

// ======================= launch =======================
extern "C" void kernel_launch(void* const* d_in, const int* in_sizes, int n_in,
                              void* d_out, int out_size)
{
    (void)in_sizes; (void)n_in;
    const float* x        = (const float*)d_in[0];
    const float* e1_w     = (const float*)d_in[1];
    const float* e1_b     = (const float*)d_in[2];
    const float* e2_w     = (const float*)d_in[3];
    const float* e2_b     = (const float*)d_in[4];
    const float* e3_w     = (const float*)d_in[5];
    const float* e3_b     = (const float*)d_in[6];
    const float* enc_rw1  = (const float*)d_in[7];
    const float* enc_rb1  = (const float*)d_in[8];
    const float* enc_rw2  = (const float*)d_in[9];
    const float* enc_rb2  = (const float*)d_in[10];
    const float* lat_w    = (const float*)d_in[11];
    const float* lat_b    = (const float*)d_in[12];
    const float* bn_gamma = (const float*)d_in[13];
    const float* bn_beta  = (const float*)d_in[14];
    const float* bn_mean  = (const float*)d_in[15];
    const float* bn_var   = (const float*)d_in[16];
    const float* codebook = (const float*)d_in[17];
    const float* din_w    = (const float*)d_in[18];
    const float* din_b    = (const float*)d_in[19];
    const float* dec_rw1  = (const float*)d_in[20];
    const float* dec_rb1  = (const float*)d_in[21];
    const float* dec_rw2  = (const float*)d_in[22];
    const float* dec_rb2  = (const float*)d_in[23];
    const float* d1_w     = (const float*)d_in[24];
    const float* d1_b     = (const float*)d_in[25];
    const float* d2_w     = (const float*)d_in[26];
    const float* d2_b     = (const float*)d_in[27];
    const float* d3_w     = (const float*)d_in[28];
    const float* d3_b     = (const float*)d_in[29];

    void* p;
    float *a, *b, *c, *t, *z, *zq, *d, *scores, *cbn, *hist, *commit, *bnsc, *bnsh;
    __nv_bfloat16 *nhHi, *nhLo, *nh2Hi, *nh2Lo, *wHi, *wLo, *eHi, *eLo, *wd1Hi, *wd1Lo, *wd2Hi, *wd2Lo;
    int* idx;
    cudaGetSymbolAddress(&p, g_a);      a      = (float*)p;
    cudaGetSymbolAddress(&p, g_b);      b      = (float*)p;
    cudaGetSymbolAddress(&p, g_c);      c      = (float*)p;
    cudaGetSymbolAddress(&p, g_t);      t      = (float*)p;
    cudaGetSymbolAddress(&p, g_z);      z      = (float*)p;
    cudaGetSymbolAddress(&p, g_zq);     zq     = (float*)p;
    cudaGetSymbolAddress(&p, g_d);      d      = (float*)p;
    cudaGetSymbolAddress(&p, g_scores); scores = (float*)p;
    cudaGetSymbolAddress(&p, g_idx);    idx    = (int*)p;
    cudaGetSymbolAddress(&p, g_cbnorm); cbn    = (float*)p;
    cudaGetSymbolAddress(&p, g_hist);   hist   = (float*)p;
    cudaGetSymbolAddress(&p, g_commit); commit = (float*)p;
    cudaGetSymbolAddress(&p, g_bnscale); bnsc  = (float*)p;
    cudaGetSymbolAddress(&p, g_bnshift); bnsh  = (float*)p;
    cudaGetSymbolAddress(&p, g_nh_hi);  nhHi   = (__nv_bfloat16*)p;
    cudaGetSymbolAddress(&p, g_nh_lo);  nhLo   = (__nv_bfloat16*)p;
    cudaGetSymbolAddress(&p, g_nh2_hi); nh2Hi  = (__nv_bfloat16*)p;
    cudaGetSymbolAddress(&p, g_nh2_lo); nh2Lo  = (__nv_bfloat16*)p;
    cudaGetSymbolAddress(&p, g_w_hi);   wHi    = (__nv_bfloat16*)p;
    cudaGetSymbolAddress(&p, g_w_lo);   wLo    = (__nv_bfloat16*)p;
    cudaGetSymbolAddress(&p, g_e_hi);   eHi    = (__nv_bfloat16*)p;
    cudaGetSymbolAddress(&p, g_e_lo);   eLo    = (__nv_bfloat16*)p;
    cudaGetSymbolAddress(&p, g_wd1_hi); wd1Hi  = (__nv_bfloat16*)p;
    cudaGetSymbolAddress(&p, g_wd1_lo); wd1Lo  = (__nv_bfloat16*)p;
    cudaGetSymbolAddress(&p, g_wd2_hi); wd2Hi  = (__nv_bfloat16*)p;
    cudaGetSymbolAddress(&p, g_wd2_lo); wd2Lo  = (__nv_bfloat16*)p;

    float* out = (float*)d_out;

    cudaFuncSetAttribute(gemm_conv3<false, 1>, cudaFuncAttributeMaxDynamicSharedMemorySize, GSM_TOTAL);
    cudaFuncSetAttribute(gemm_conv3<true, 2>,  cudaFuncAttributeMaxDynamicSharedMemorySize, GSM_TOTAL);
    cudaFuncSetAttribute(gemm_conv3<true, 3>,  cudaFuncAttributeMaxDynamicSharedMemorySize, GSM_TOTAL);
    cudaFuncSetAttribute(gemm_deconv<32, 256, true>,  cudaFuncAttributeMaxDynamicSharedMemorySize, GSM_TOTAL);
    cudaFuncSetAttribute(gemm_deconv<64, 128, false>, cudaFuncAttributeMaxDynamicSharedMemorySize, GSM_TOTAL);

    // ---- prep ----
    zero_halo2<<<16 * 132, 256>>>(nhHi, nhLo, nh2Hi, nh2Lo);
    zero_halo66<<<16 * 260, 256>>>(eHi, eLo);
    prep_wsplit<<<(8 * 9 * 65536 + 255) / 256, 256>>>(dec_rw1, dec_rw2, wHi, wLo);
    prep_wsplit_dc<<<4096, 256>>>(d1_w, wd1Hi, wd1Lo, 256);
    prep_wsplit_dc<<<2048, 256>>>(d2_w, wd2Hi, wd2Lo, 128);

    // ---- encoder: three stride-2 4x4 convs, relu ----
    conv_generic<4, 2, 1, 4, false, true, false, false>
        <<<dim3(16, 32, 16), 128>>>(x, e1_w, e1_b, a, 3, 128, 256, 256, 128, 128, 4, nullptr, nullptr);
    conv4s2_pipe<<<dim3(8, 32, 16), 64>>>(a, e2_w, e2_b, b, 128, 128, 128, 128, 2);
    conv4s2_pipe<<<dim3(2, 64, 16), 64>>>(b, e3_w, e3_b, c, 128, 256, 64, 64, 1);

    // ---- encoder resblocks (exact fp32 SIMT — feeds the VQ argmin) ----
    for (int i = 0; i < 4; i++) {
        const float* w1 = enc_rw1 + (size_t)i * 256 * 256 * 9;
        const float* b1 = enc_rb1 + (size_t)i * 256;
        const float* w2 = enc_rw2 + (size_t)i * 256 * 256 * 9;
        const float* b2 = enc_rb2 + (size_t)i * 256;
        conv3_pipe<true, false><<<dim3(2, 32, 16), 64>>>(c, w1, b1, t, 256, 256);
        conv3_pipe<true, true><<<dim3(2, 32, 16), 64>>>(t, w2, b2, c, 256, 256);
    }

    // ---- latent 1x1 conv + folded BN ----
    bn_prep<<<1, 128>>>(bn_gamma, bn_beta, bn_mean, bn_var, bnsc, bnsh);
    conv_generic<1, 1, 8, 8, false, false, false, true>
        <<<dim3(1, 16, 16), 128>>>(c, lat_w, lat_b, z, 256, 128, 32, 32, 32, 32, 1, bnsc, bnsh);

    // ---- VQ ----
    vq_cbnorm<<<2, 256>>>(codebook, cbn);
    vq_init<<<1, 512>>>(hist, commit);
    vq_gemm<<<dim3(128, 8), 256>>>(z, codebook, scores);
    vq_argmin<<<2048, 256>>>(scores, cbn, idx);
    vq_gather<<<64, 256>>>(z, codebook, idx, zq, hist, commit);

    // ---- decoder 1x1 ----
    conv_generic<1, 1, 8, 8, false, false, false, false>
        <<<dim3(1, 32, 16), 128>>>(zq, din_w, din_b, d, 128, 256, 32, 32, 32, 32, 1, nullptr, nullptr);

    const size_t WSET = (size_t)9 * 65536;
    // ---- decoder resblocks (bf16-split GEMM, fused split epilogues, A/B ping-pong) ----
    split_nhwc<<<512, 256>>>(d, nhHi, nhLo);   // initial: relu(d) -> A
    for (int i = 0; i < 4; i++) {
        // conv1: A -> relu'd hi/lo in B (no fp32 out)
        gemm_conv3<false, 1><<<128, 512, GSM_TOTAL>>>(nhHi, nhLo,
            wHi + (size_t)i * WSET, wLo + (size_t)i * WSET,
            dec_rb1 + (size_t)i * 256, t, nh2Hi, nh2Lo);
        // conv2: B (+d residual) -> d fp32 (if needed) + hi/lo in A
        if (i < 3)
            gemm_conv3<true, 2><<<128, 512, GSM_TOTAL>>>(nh2Hi, nh2Lo,
                wHi + (size_t)(4 + i) * WSET, wLo + (size_t)(4 + i) * WSET,
                dec_rb2 + (size_t)i * 256, d, nhHi, nhLo);
        else
            gemm_conv3<true, 3><<<128, 512, GSM_TOTAL>>>(nh2Hi, nh2Lo,
                wHi + (size_t)(4 + i) * WSET, wLo + (size_t)(4 + i) * WSET,
                dec_rb2 + (size_t)i * 256, d, nhHi, nhLo);
    }

    // ---- decoder deconvs: d1 reads non-relu split in A; d2; d3 fp32 ----
    gemm_deconv<32, 256, true><<<dim3(128, 4), 512, GSM_TOTAL>>>(
        nhHi, nhLo, wd1Hi, wd1Lo, d1_b, eHi, eLo, nullptr);
    gemm_deconv<64, 128, false><<<dim3(256, 4), 512, GSM_TOTAL>>>(
        eHi, eLo, wd2Hi, wd2Lo, d2_b, nullptr, nullptr, a);
    deconv_pipe<false><<<dim3(32, 2, 16), 128>>>(a, d3_w, d3_b, out, 128, 5, 128, 128, 4);

    // ---- scalars (vq_loss, perplexity) appended after recon ----
    if (out_size >= 5242882) {
        vq_finalize<<<1, 512>>>(hist, commit, out + 5242880);
    }
}

// round 14
// speedup vs baseline: 1.0714x; 1.0714x over previous
#include <cuda_runtime.h>
#include <cuda_bf16.h>
#include <math.h>
#include <stdint.h>

// ======================= scratch (device globals; no allocs) =======================
__device__ float g_a[33554432];   // 16*128*128*128
__device__ float g_b[8388608];    // 16*128*64*64
__device__ float g_c[4194304];    // 16*256*32*32 encoder chain
__device__ float g_t[4194304];    // resblock tmp
__device__ float g_z[2097152];
__device__ float g_zq[2097152];
__device__ float g_d[4194304];    // decoder chain
__device__ float g_scores[8388608];
__device__ int   g_idx[16384];
__device__ float g_cbnorm[512];
__device__ float g_hist[512];
__device__ float g_commit;
__device__ float g_bnscale[128];
__device__ float g_bnshift[128];
// tensor-core path buffers
__device__ __nv_bfloat16 g_nh_hi[4734976];   // 16*34*34*256 padded NHWC
__device__ __nv_bfloat16 g_nh_lo[4734976];
__device__ __nv_bfloat16 g_w_hi[4718592];    // 8 sets * 9 taps * 256 oc * 256 ci
__device__ __nv_bfloat16 g_w_lo[4718592];
__device__ __nv_bfloat16 g_e_hi[17842176];   // 16*66*66*256 padded NHWC (deconv1 out)
__device__ __nv_bfloat16 g_e_lo[17842176];
__device__ __nv_bfloat16 g_wd1_hi[1048576];  // 4 phases * 4 taps * 256 oc * 256 ci
__device__ __nv_bfloat16 g_wd1_lo[1048576];
__device__ __nv_bfloat16 g_wd2_hi[524288];   // 4 phases * 4 taps * 128 oc * 256 ci
__device__ __nv_bfloat16 g_wd2_lo[524288];

// ======================= helpers =======================
__device__ __forceinline__ uint32_t smem_u32(const void* p) {
    return (uint32_t)__cvta_generic_to_shared(p);
}
__device__ __forceinline__ void cp16(uint32_t d, const void* s, bool pred) {
    int sz = pred ? 16 : 0;
    asm volatile("cp.async.ca.shared.global [%0], [%1], 16, %2;\n" :: "r"(d), "l"(s), "r"(sz));
}
__device__ __forceinline__ void cp4(uint32_t d, const void* s, bool pred) {
    int sz = pred ? 4 : 0;
    asm volatile("cp.async.ca.shared.global [%0], [%1], 4, %2;\n" :: "r"(d), "l"(s), "r"(sz));
}
__device__ __forceinline__ void cp_commit() { asm volatile("cp.async.commit_group;\n"); }
__device__ __forceinline__ void cp_wait1()  { asm volatile("cp.async.wait_group 1;\n"); }
__device__ __forceinline__ void cp_wait0()  { asm volatile("cp.async.wait_group 0;\n"); }

__device__ __forceinline__ void ldm4(uint32_t* r, uint32_t addr) {
    asm volatile("ldmatrix.sync.aligned.m8n8.x4.shared.b16 {%0,%1,%2,%3}, [%4];"
        : "=r"(r[0]), "=r"(r[1]), "=r"(r[2]), "=r"(r[3]) : "r"(addr));
}
__device__ __forceinline__ void mma16816(float* d, const uint32_t* a, uint32_t b0, uint32_t b1) {
    asm volatile("mma.sync.aligned.m16n8k16.row.col.f32.bf16.bf16.f32 "
        "{%0,%1,%2,%3}, {%4,%5,%6,%7}, {%8,%9}, {%0,%1,%2,%3};"
        : "+f"(d[0]), "+f"(d[1]), "+f"(d[2]), "+f"(d[3])
        : "r"(a[0]), "r"(a[1]), "r"(a[2]), "r"(a[3]), "r"(b0), "r"(b1));
}

// ======================= prep kernels =======================
__global__ void zero_halo(__nv_bfloat16* __restrict__ hi, __nv_bfloat16* __restrict__ lo)
{
    int b = blockIdx.x;               // 16*132
    int n = b / 132, i = b - n * 132;
    int y, x;
    if (i < 34)       { y = 0;  x = i; }
    else if (i < 68)  { y = 33; x = i - 34; }
    else if (i < 100) { y = i - 68 + 1;  x = 0; }
    else              { y = i - 100 + 1; x = 33; }
    size_t p = ((size_t)(n * 34 + y) * 34 + x) * 256 + threadIdx.x;
    hi[p] = __float2bfloat16(0.f);
    lo[p] = __float2bfloat16(0.f);
}

__global__ void zero_halo66(__nv_bfloat16* __restrict__ hi, __nv_bfloat16* __restrict__ lo)
{
    int b = blockIdx.x;               // 16*260
    int n = b / 260, i = b - n * 260;
    int y, x;
    if (i < 66)        { y = 0;  x = i; }
    else if (i < 132)  { y = 65; x = i - 66; }
    else if (i < 196)  { y = i - 132 + 1; x = 0; }
    else               { y = i - 196 + 1; x = 65; }
    size_t p = ((size_t)(n * 66 + y) * 66 + x) * 256 + threadIdx.x;
    hi[p] = __float2bfloat16(0.f);
    lo[p] = __float2bfloat16(0.f);
}

// 8 sets: dec_rw1 (0-3), dec_rw2 (4-7)
__global__ void prep_wsplit(const float* __restrict__ d1, const float* __restrict__ d2,
                            __nv_bfloat16* __restrict__ hi, __nv_bfloat16* __restrict__ lo)
{
    int t = blockIdx.x * 256 + threadIdx.x;
    if (t >= 8 * 9 * 65536) return;
    int ci = t & 255;
    int oc = (t >> 8) & 255;
    int st = t >> 16;            // s*9 + tap
    int s = st / 9, tap = st - s * 9;
    const float* src = (s < 4) ? d1 : d2;
    int i = s & 3;
    float v = src[(((size_t)(i * 256 + oc) * 256 + ci) * 9) + tap];
    __nv_bfloat16 h = __float2bfloat16(v);
    hi[t] = h;
    lo[t] = __float2bfloat16(v - __bfloat162float(h));
}

// deconv weight split: phase/tap layout [ph*4+tt][oc][ci]
__global__ void prep_wsplit_dc(const float* __restrict__ w,
                               __nv_bfloat16* __restrict__ hi, __nv_bfloat16* __restrict__ lo,
                               int NOC)
{
    int t = blockIdx.x * 256 + threadIdx.x;
    if (t >= 16 * NOC * 256) return;
    int ci = t & 255;
    int rest = t >> 8;
    int oc = rest % NOC;
    int pt = rest / NOC;          // ph*4 + tt
    int ph = pt >> 2, tt = pt & 3;
    int a = ph >> 1, b = ph & 1;
    int kh = a + 2 * (tt >> 1);
    int kw = b + 2 * (tt & 1);
    float v = w[((size_t)oc * 256 + ci) * 16 + kh * 4 + kw];
    __nv_bfloat16 h = __float2bfloat16(v);
    hi[t] = h;
    lo[t] = __float2bfloat16(v - __bfloat162float(h));
}

// optional-relu fp32->bf16 hi/lo split, NCHW -> 34x34 padded NHWC
template<bool RELU>
__global__ __launch_bounds__(256)
void split_nhwc(const float* __restrict__ act, __nv_bfloat16* __restrict__ hi, __nv_bfloat16* __restrict__ lo)
{
    __shared__ float s[256][33];
    int b = blockIdx.x;          // 0..511
    int n = b >> 5, y = b & 31;
    const float* a = act + ((size_t)n * 262144) + y * 32;
    for (int idx = threadIdx.x; idx < 8192; idx += 256) {
        int ci = idx >> 5, x = idx & 31;
        s[ci][x] = a[(size_t)ci * 1024 + x];
    }
    __syncthreads();
    size_t pbase = ((size_t)(n * 34 + y + 1) * 34 + 1) * 256;
    for (int idx = threadIdx.x; idx < 8192; idx += 256) {
        int x = idx >> 8, ci = idx & 255;
        float v = s[ci][x];
        if (RELU) v = fmaxf(v, 0.f);
        __nv_bfloat16 h = __float2bfloat16(v);
        float rem = v - __bfloat162float(h);
        hi[pbase + (size_t)x * 256 + ci] = h;
        lo[pbase + (size_t)x * 256 + ci] = __float2bfloat16(rem);
    }
}

// ======================= mma.sync implicit-GEMM 3x3 conv (decoder resblocks) =======================
static constexpr int GSM_TOTAL = 122880;

template<bool ADD>
__global__ __launch_bounds__(512, 1)
void gemm_conv3(const __nv_bfloat16* __restrict__ ahi, const __nv_bfloat16* __restrict__ alo,
                const __nv_bfloat16* __restrict__ bhi, const __nv_bfloat16* __restrict__ blo,
                const float* __restrict__ bias, float* __restrict__ out)
{
    extern __shared__ char smem[];
    const uint32_t sbase = smem_u32(smem);
    const int tid = threadIdx.x;
    const int tile = blockIdx.x;       // 0..127
    const int n = tile >> 3;
    const int y0 = (tile & 7) << 2;

    const __nv_bfloat16* aHiN = ahi + (size_t)n * 295936;
    const __nv_bfloat16* aLoN = alo + (size_t)n * 295936;

    auto loadChunk = [&](int s, int st) {
        int tap = s >> 3;
        int c0 = (s & 7) << 5;
        int kh = tap / 3, kw = tap - kh * 3;
        uint32_t sb = sbase + (uint32_t)st * 61440u;
        {
            int r = tid >> 2, seg = tid & 3;
            int yy = y0 + (r >> 5) + kh, xx = (r & 31) + kw;
            size_t src = (size_t)(yy * 34 + xx) * 256 + c0 + seg * 8;
            uint32_t d = (uint32_t)(r * 80 + seg * 16);
            cp16(sb + d, aHiN + src, true);
            cp16(sb + 10240u + d, aLoN + src, true);
        }
        const __nv_bfloat16* bh = bhi + ((size_t)tap << 16) + c0;
        const __nv_bfloat16* bl = blo + ((size_t)tap << 16) + c0;
        for (int j = tid; j < 1024; j += 512) {
            int oc = j >> 2, seg = j & 3;
            size_t src = ((size_t)oc << 8) + seg * 8;
            uint32_t d = (uint32_t)(oc * 80 + seg * 16);
            cp16(sb + 20480u + d, bh + src, true);
            cp16(sb + 40960u + d, bl + src, true);
        }
        cp_commit();
    };

    const int w = tid >> 5, lane = tid & 31;
    const int wm = (w >> 2) << 5;
    const int wn = (w & 3) << 6;

    float acc[16][4];
#pragma unroll
    for (int i = 0; i < 16; i++)
#pragma unroll
        for (int j = 0; j < 4; j++) acc[i][j] = 0.f;

    const uint32_t aoff = (uint32_t)((wm + (lane & 15)) * 80 + ((lane >> 4) << 4));
    uint32_t boff[4];
    {
        int nloc = (lane & 7) + ((lane >> 4) & 1) * 8;
        int kb = ((lane >> 3) & 1) * 16;
#pragma unroll
        for (int j = 0; j < 4; j++)
            boff[j] = (uint32_t)((wn + j * 16 + nloc) * 80 + kb);
    }

    loadChunk(0, 0);
    loadChunk(1, 1);

    const int T = 72;
    for (int s = 0; s < T; s++) {
        int st = s & 1;
        if (s == T - 1) cp_wait0(); else cp_wait1();
        __syncthreads();
        uint32_t sb = sbase + (uint32_t)st * 61440u;
#pragma unroll
        for (int kk = 0; kk < 2; kk++) {
            uint32_t k32 = kk * 32;
            uint32_t ah[2][4], al[2][4], bb[16];
            ldm4(ah[0], sb + aoff + k32);
            ldm4(ah[1], sb + 1280u + aoff + k32);
            ldm4(al[0], sb + 10240u + aoff + k32);
            ldm4(al[1], sb + 11520u + aoff + k32);
#pragma unroll
            for (int j = 0; j < 4; j++) ldm4(&bb[4 * j], sb + 20480u + boff[j] + k32);
#pragma unroll
            for (int nt = 0; nt < 8; nt++)
#pragma unroll
                for (int mt = 0; mt < 2; mt++)
                    mma16816(acc[mt * 8 + nt], ah[mt], bb[2 * nt], bb[2 * nt + 1]);
#pragma unroll
            for (int nt = 0; nt < 8; nt++)
#pragma unroll
                for (int mt = 0; mt < 2; mt++)
                    mma16816(acc[mt * 8 + nt], al[mt], bb[2 * nt], bb[2 * nt + 1]);
#pragma unroll
            for (int j = 0; j < 4; j++) ldm4(&bb[4 * j], sb + 40960u + boff[j] + k32);
#pragma unroll
            for (int nt = 0; nt < 8; nt++)
#pragma unroll
                for (int mt = 0; mt < 2; mt++)
                    mma16816(acc[mt * 8 + nt], ah[mt], bb[2 * nt], bb[2 * nt + 1]);
        }
        __syncthreads();
        if (s + 2 < T) loadChunk(s + 2, st);
    }

    const int mrow = lane >> 2;
    const int ncol = (lane & 3) << 1;
    const size_t obase = (size_t)n * 262144 + (size_t)(y0 * 32);
#pragma unroll
    for (int mt = 0; mt < 2; mt++)
#pragma unroll
        for (int nt = 0; nt < 8; nt++) {
            const float* dd = acc[mt * 8 + nt];
            int m = wm + mt * 16 + mrow;
            int oc = wn + nt * 8 + ncol;
            float b0 = __ldg(bias + oc), b1 = __ldg(bias + oc + 1);
            size_t o00 = obase + (size_t)oc * 1024 + m;
            size_t o01 = o00 + 1024;
            size_t o10 = o00 + 8;
            size_t o11 = o01 + 8;
            float v0 = dd[0] + b0, v1 = dd[1] + b1, v2 = dd[2] + b0, v3 = dd[3] + b1;
            if (ADD) { v0 += out[o00]; v1 += out[o01]; v2 += out[o10]; v3 += out[o11]; }
            out[o00] = v0; out[o01] = v1; out[o10] = v2; out[o11] = v3;
        }
}

// ======================= mma.sync implicit-GEMM transposed conv (d1, d2) =======================
template<int WIDTH, int NOC, bool SPLIT_OUT>
__global__ __launch_bounds__(512, 1)
void gemm_deconv(const __nv_bfloat16* __restrict__ ahi, const __nv_bfloat16* __restrict__ alo,
                 const __nv_bfloat16* __restrict__ bhi, const __nv_bfloat16* __restrict__ blo,
                 const float* __restrict__ bias,
                 __nv_bfloat16* __restrict__ ohi, __nv_bfloat16* __restrict__ olo,
                 float* __restrict__ out)
{
    constexpr int MT = 4 * WIDTH;
    constexpr int PW = WIDTH + 2;
    constexpr int WN_WARPS = NOC / 64;
    constexpr uint32_t A_LO = MT * 80;
    constexpr uint32_t B_HI = 2 * MT * 80;
    constexpr uint32_t B_LO = B_HI + NOC * 80;
    constexpr int YTILES = WIDTH / 4;

    extern __shared__ char smem[];
    const uint32_t sbase = smem_u32(smem);
    const int tid = threadIdx.x;
    const int n = blockIdx.x / YTILES;
    const int y0 = (blockIdx.x % YTILES) * 4;
    const int ph = blockIdx.y;
    const int pa = ph >> 1, pb = ph & 1;

    const size_t imgStride = (size_t)PW * PW * 256;
    const __nv_bfloat16* aHiN = ahi + (size_t)n * imgStride;
    const __nv_bfloat16* aLoN = alo + (size_t)n * imgStride;

    auto loadChunk = [&](int s, int st) {
        int tt = s >> 3;
        int c0 = (s & 7) << 5;
        int dy = pa - 1 + (tt >> 1);
        int dx = pb - 1 + (tt & 1);
        uint32_t sb = sbase + (uint32_t)st * 61440u;
        for (int j = tid; j < MT * 4; j += 512) {
            int r = j >> 2, seg = j & 3;
            int yy = y0 + r / WIDTH + dy + 1;
            int xx = r % WIDTH + dx + 1;
            size_t src = (size_t)(yy * PW + xx) * 256 + c0 + seg * 8;
            uint32_t d = (uint32_t)(r * 80 + seg * 16);
            cp16(sb + d, aHiN + src, true);
            cp16(sb + A_LO + d, aLoN + src, true);
        }
        const __nv_bfloat16* bh = bhi + ((size_t)(ph * 4 + tt) * NOC << 8) + c0;
        const __nv_bfloat16* bl = blo + ((size_t)(ph * 4 + tt) * NOC << 8) + c0;
        for (int j = tid; j < NOC * 4; j += 512) {
            int oc = j >> 2, seg = j & 3;
            size_t src = ((size_t)oc << 8) + seg * 8;
            uint32_t d = (uint32_t)(oc * 80 + seg * 16);
            cp16(sb + B_HI + d, bh + src, true);
            cp16(sb + B_LO + d, bl + src, true);
        }
        cp_commit();
    };

    const int w = tid >> 5, lane = tid & 31;
    const int wm = (w / WN_WARPS) << 5;
    const int wn = (w % WN_WARPS) << 6;

    float acc[16][4];
#pragma unroll
    for (int i = 0; i < 16; i++)
#pragma unroll
        for (int j = 0; j < 4; j++) acc[i][j] = 0.f;

    const uint32_t aoff = (uint32_t)((wm + (lane & 15)) * 80 + ((lane >> 4) << 4));
    uint32_t boff[4];
    {
        int nloc = (lane & 7) + ((lane >> 4) & 1) * 8;
        int kb = ((lane >> 3) & 1) * 16;
#pragma unroll
        for (int j = 0; j < 4; j++)
            boff[j] = (uint32_t)((wn + j * 16 + nloc) * 80 + kb);
    }

    loadChunk(0, 0);
    loadChunk(1, 1);

    const int T = 32;
    for (int s = 0; s < T; s++) {
        int st = s & 1;
        if (s == T - 1) cp_wait0(); else cp_wait1();
        __syncthreads();
        uint32_t sb = sbase + (uint32_t)st * 61440u;
#pragma unroll
        for (int kk = 0; kk < 2; kk++) {
            uint32_t k32 = kk * 32;
            uint32_t ah[2][4], al[2][4], bb[16];
            ldm4(ah[0], sb + aoff + k32);
            ldm4(ah[1], sb + 1280u + aoff + k32);
            ldm4(al[0], sb + A_LO + aoff + k32);
            ldm4(al[1], sb + A_LO + 1280u + aoff + k32);
#pragma unroll
            for (int j = 0; j < 4; j++) ldm4(&bb[4 * j], sb + B_HI + boff[j] + k32);
#pragma unroll
            for (int nt = 0; nt < 8; nt++)
#pragma unroll
                for (int mt = 0; mt < 2; mt++)
                    mma16816(acc[mt * 8 + nt], ah[mt], bb[2 * nt], bb[2 * nt + 1]);
#pragma unroll
            for (int nt = 0; nt < 8; nt++)
#pragma unroll
                for (int mt = 0; mt < 2; mt++)
                    mma16816(acc[mt * 8 + nt], al[mt], bb[2 * nt], bb[2 * nt + 1]);
#pragma unroll
            for (int j = 0; j < 4; j++) ldm4(&bb[4 * j], sb + B_LO + boff[j] + k32);
#pragma unroll
            for (int nt = 0; nt < 8; nt++)
#pragma unroll
                for (int mt = 0; mt < 2; mt++)
                    mma16816(acc[mt * 8 + nt], ah[mt], bb[2 * nt], bb[2 * nt + 1]);
        }
        __syncthreads();
        if (s + 2 < T) loadChunk(s + 2, st);
    }

    const int mrow = lane >> 2;
    const int ncol = (lane & 3) << 1;
#pragma unroll
    for (int mt = 0; mt < 2; mt++)
#pragma unroll
        for (int nt = 0; nt < 8; nt++) {
            const float* dd = acc[mt * 8 + nt];
            int oc = wn + nt * 8 + ncol;
            float b0 = __ldg(bias + oc), b1 = __ldg(bias + oc + 1);
#pragma unroll
            for (int half = 0; half < 2; half++) {
                int m = wm + mt * 16 + mrow + half * 8;
                int iy = y0 + m / WIDTH, jx = m % WIDTH;
                int oy = 2 * iy + pa, ox = 2 * jx + pb;
                float v0 = fmaxf(dd[half * 2 + 0] + b0, 0.f);
                float v1 = fmaxf(dd[half * 2 + 1] + b1, 0.f);
                if (SPLIT_OUT) {
                    size_t p = ((size_t)(n * 66 + oy + 1) * 66 + ox + 1) * 256 + oc;
                    __nv_bfloat16 h0 = __float2bfloat16(v0);
                    __nv_bfloat16 h1 = __float2bfloat16(v1);
                    ohi[p] = h0; ohi[p + 1] = h1;
                    olo[p]     = __float2bfloat16(v0 - __bfloat162float(h0));
                    olo[p + 1] = __float2bfloat16(v1 - __bfloat162float(h1));
                } else {
                    size_t o = (((size_t)n * NOC + oc) * (2 * WIDTH) + oy) * (2 * WIDTH) + ox;
                    out[o] = v0;
                    out[o + (size_t)(2 * WIDTH) * (2 * WIDTH)] = v1;
                }
            }
        }
}

// ======================= pipelined 3x3 conv (encoder resblocks, exact fp32) =======================
template<bool RELU_IN, bool RELU_OUT, bool ADD>
__global__ __launch_bounds__(64)
void conv3_pipe(const float* __restrict__ in, const float* __restrict__ wgt,
                const float* __restrict__ bias, float* __restrict__ out,
                int Cin, int Cout)
{
    constexpr int CI = 4;
    __shared__ __align__(16) float s_in[2][CI][18][36];
    __shared__ __align__(16) float s_w[2][8][CI][12];

    const int tY  = blockIdx.x;
    const int oc0 = blockIdx.y * 8;
    const int n   = blockIdx.z;
    const int tid = threadIdx.x;
    const int ty  = tid >> 3, tx = tid & 7;
    const int iR0 = tY * 16 - 1;

    const float* inN = in + (size_t)n * Cin * 1024;
    const int nCh = Cin / CI;

    for (int i = tid; i < 2 * CI * 18; i += 64) {
        int st = i / (CI * 18);
        int r  = i % (CI * 18);
        int ci = r / 18, rr = r % 18;
        float4 z4 = {0.f, 0.f, 0.f, 0.f};
        *(float4*)&s_in[st][ci][rr][32] = z4;
    }

    auto prefetch = [&](int ch, int st) {
        const float* gi = inN + (size_t)ch * CI * 1024;
        for (int k = tid; k < CI * 18 * 8; k += 64) {
            int ci = k / 144;
            int rem = k - ci * 144;
            int r = rem >> 3, j = rem & 7;
            int gr = iR0 + r;
            bool p = (unsigned)gr < 32u;
            int grc = p ? gr : 0;
            cp16(smem_u32(&s_in[st][ci][r][4 * j]), gi + ci * 1024 + grc * 32 + 4 * j, p);
        }
        if (tid < 32) {
            int oc = tid >> 2, ci = tid & 3;
            const float* gw = wgt + ((size_t)(oc0 + oc) * Cin + ch * CI + ci) * 9;
            uint32_t d = smem_u32(&s_w[st][oc][ci][0]);
#pragma unroll
            for (int w = 0; w < 9; w++) cp4(d + 4 * w, gw + w, true);
        }
    };

    float acc[8][2][4];
#pragma unroll
    for (int o = 0; o < 8; o++)
#pragma unroll
        for (int r = 0; r < 2; r++)
#pragma unroll
            for (int c = 0; c < 4; c++) acc[o][r][c] = 0.f;

    prefetch(0, 0);
    cp_commit();

    const int lidx = (tx == 0) ? 34 : (4 * tx - 1);

    for (int ch = 0; ch < nCh; ch++) {
        int st = ch & 1;
        if (ch + 1 < nCh) { prefetch(ch + 1, st ^ 1); cp_commit(); cp_wait1(); }
        else              { cp_wait0(); }
        __syncthreads();
#pragma unroll 1
        for (int ci = 0; ci < CI; ci++) {
            float rin[4][6];
#pragma unroll
            for (int rr = 0; rr < 4; rr++) {
                int r = 2 * ty + rr;
                float l = s_in[st][ci][r][lidx];
                float4 m = *(const float4*)&s_in[st][ci][r][4 * tx];
                float rg = s_in[st][ci][r][4 * tx + 4];
                rin[rr][0] = l; rin[rr][1] = m.x; rin[rr][2] = m.y;
                rin[rr][3] = m.z; rin[rr][4] = m.w; rin[rr][5] = rg;
                if (RELU_IN) {
#pragma unroll
                    for (int u = 0; u < 6; u++) rin[rr][u] = fmaxf(rin[rr][u], 0.f);
                }
            }
#pragma unroll
            for (int oc = 0; oc < 8; oc++) {
                float wk[9];
                float4 w0 = *(const float4*)&s_w[st][oc][ci][0];
                float4 w1 = *(const float4*)&s_w[st][oc][ci][4];
                wk[0] = w0.x; wk[1] = w0.y; wk[2] = w0.z; wk[3] = w0.w;
                wk[4] = w1.x; wk[5] = w1.y; wk[6] = w1.z; wk[7] = w1.w;
                wk[8] = s_w[st][oc][ci][8];
#pragma unroll
                for (int ry = 0; ry < 2; ry++)
#pragma unroll
                    for (int cx = 0; cx < 4; cx++) {
                        float a = acc[oc][ry][cx];
#pragma unroll
                        for (int kh = 0; kh < 3; kh++)
#pragma unroll
                            for (int kw = 0; kw < 3; kw++)
                                a = fmaf(rin[ry + kh][cx + kw], wk[kh * 3 + kw], a);
                        acc[oc][ry][cx] = a;
                    }
            }
        }
        __syncthreads();
    }

#pragma unroll
    for (int oc = 0; oc < 8; oc++) {
        int ocg = oc0 + oc;
        float bv = bias[ocg];
#pragma unroll
        for (int ry = 0; ry < 2; ry++) {
            int R = 16 * tY + 2 * ty + ry;
            size_t o = (((size_t)n * Cout + ocg) * 32 + R) * 32 + 4 * tx;
            float4 v;
            v.x = acc[oc][ry][0] + bv; v.y = acc[oc][ry][1] + bv;
            v.z = acc[oc][ry][2] + bv; v.w = acc[oc][ry][3] + bv;
            if (ADD) {
                float4 p = *(const float4*)&out[o];
                v.x += p.x; v.y += p.y; v.z += p.z; v.w += p.w;
            }
            if (RELU_OUT) {
                v.x = fmaxf(v.x, 0.f); v.y = fmaxf(v.y, 0.f);
                v.z = fmaxf(v.z, 0.f); v.w = fmaxf(v.w, 0.f);
            }
            *(float4*)&out[o] = v;
        }
    }
}

// ======================= pipelined 4x4 stride-2 conv (e2, e3), OCPT=8 =======================
__global__ __launch_bounds__(64)
void conv4s2_pipe(const float* __restrict__ in, const float* __restrict__ wgt,
                  const float* __restrict__ bias, float* __restrict__ out,
                  int Cin, int Cout, int Hin, int Win, int tilesX)
{
    constexpr int CI = 2;
    __shared__ __align__(16) float s_in[2][CI][34][68];
    __shared__ __align__(16) float s_w[2][8][CI][16];

    const int tY   = blockIdx.x / tilesX;
    const int tX   = blockIdx.x - tY * tilesX;
    const int oc0  = blockIdx.y * 8;
    const int n    = blockIdx.z;
    const int tid  = threadIdx.x;
    const int ty   = tid >> 3, tx = tid & 7;
    const int iR0  = tY * 32 - 1;
    const int gc0  = tX * 64;
    const int Hout = Hin >> 1, Wout = Win >> 1;

    const float* inN = in + (size_t)n * Cin * Hin * Win;
    const int nCh = Cin / CI;

    auto prefetch = [&](int ch, int st) {
        const float* gi = inN + (size_t)ch * CI * Hin * Win;
        for (int k = tid; k < CI * 34 * 16; k += 64) {
            int ci = k / 544;
            int rem = k - ci * 544;
            int r = rem >> 4, j = rem & 15;
            int gr = iR0 + r;
            bool p = (unsigned)gr < (unsigned)Hin;
            int grc = p ? gr : 0;
            cp16(smem_u32(&s_in[st][ci][r][4 * j]), gi + (size_t)ci * Hin * Win + (size_t)grc * Win + gc0 + 4 * j, p);
        }
        for (int k = tid; k < CI * 34; k += 64) {
            int ci = k / 34, r = k - ci * 34;
            int gr = iR0 + r;
            bool rok = (unsigned)gr < (unsigned)Hin;
            int grc = rok ? gr : 0;
            const float* rowp = gi + (size_t)ci * Hin * Win + (size_t)grc * Win;
            cp4(smem_u32(&s_in[st][ci][r][66]), rowp + gc0 - 1, rok && gc0 > 0);
            cp4(smem_u32(&s_in[st][ci][r][64]), rowp + gc0 + 64, rok && (gc0 + 64 < Win));
        }
        // weights: 8 oc x CI x 4 chunks -> 64 slots = all threads
        {
            int pair = tid >> 2, seg = tid & 3;
            int oc = pair / CI, ci = pair - oc * CI;
            const float* gw = wgt + ((size_t)(oc0 + oc) * Cin + ch * CI + ci) * 16 + seg * 4;
            cp16(smem_u32(&s_w[st][oc][ci][seg * 4]), gw, true);
        }
    };

    float acc[8][2][4];
#pragma unroll
    for (int o = 0; o < 8; o++)
#pragma unroll
        for (int r = 0; r < 2; r++)
#pragma unroll
            for (int c = 0; c < 4; c++) acc[o][r][c] = 0.f;

    prefetch(0, 0);
    cp_commit();

    const int lidx = (tx == 0) ? 66 : (8 * tx - 1);

    for (int ch = 0; ch < nCh; ch++) {
        int st = ch & 1;
        if (ch + 1 < nCh) { prefetch(ch + 1, st ^ 1); cp_commit(); cp_wait1(); }
        else              { cp_wait0(); }
        __syncthreads();
#pragma unroll 1
        for (int ci = 0; ci < CI; ci++) {
            float rin[6][10];
#pragma unroll
            for (int rr = 0; rr < 6; rr++) {
                int r = 4 * ty + rr;
                rin[rr][0] = s_in[st][ci][r][lidx];
                float4 m0 = *(const float4*)&s_in[st][ci][r][8 * tx];
                float4 m1 = *(const float4*)&s_in[st][ci][r][8 * tx + 4];
                rin[rr][1] = m0.x; rin[rr][2] = m0.y; rin[rr][3] = m0.z; rin[rr][4] = m0.w;
                rin[rr][5] = m1.x; rin[rr][6] = m1.y; rin[rr][7] = m1.z; rin[rr][8] = m1.w;
                rin[rr][9] = s_in[st][ci][r][8 * tx + 8];
            }
#pragma unroll
            for (int oc = 0; oc < 8; oc++) {
                float wk[16];
#pragma unroll
                for (int s4 = 0; s4 < 4; s4++) {
                    float4 w = *(const float4*)&s_w[st][oc][ci][4 * s4];
                    wk[4 * s4] = w.x; wk[4 * s4 + 1] = w.y; wk[4 * s4 + 2] = w.z; wk[4 * s4 + 3] = w.w;
                }
#pragma unroll
                for (int ry = 0; ry < 2; ry++)
#pragma unroll
                    for (int cx = 0; cx < 4; cx++) {
                        float a = acc[oc][ry][cx];
#pragma unroll
                        for (int kh = 0; kh < 4; kh++)
#pragma unroll
                            for (int kw = 0; kw < 4; kw++)
                                a = fmaf(rin[2 * ry + kh][2 * cx + kw], wk[kh * 4 + kw], a);
                        acc[oc][ry][cx] = a;
                    }
            }
        }
        __syncthreads();
    }

#pragma unroll
    for (int oc = 0; oc < 8; oc++) {
        int ocg = oc0 + oc;
        float bv = bias[ocg];
#pragma unroll
        for (int ry = 0; ry < 2; ry++) {
            int R = 16 * tY + 2 * ty + ry;
            int C = 32 * tX + 4 * tx;
            size_t o = (((size_t)n * Cout + ocg) * Hout + R) * Wout + C;
            float4 v;
            v.x = fmaxf(acc[oc][ry][0] + bv, 0.f);
            v.y = fmaxf(acc[oc][ry][1] + bv, 0.f);
            v.z = fmaxf(acc[oc][ry][2] + bv, 0.f);
            v.w = fmaxf(acc[oc][ry][3] + bv, 0.f);
            *(float4*)&out[o] = v;
        }
    }
}

// ======================= R2 pipelined transposed conv (d3 only) =======================
template<bool RELU_OUT>
__global__ __launch_bounds__(128)
void deconv_pipe(const float* __restrict__ in, const float* __restrict__ wgt,
                 const float* __restrict__ bias, float* __restrict__ out,
                 int Cin, int Cout, int Hin, int Win, int tilesX)
{
    constexpr int CI = 4;
    __shared__ __align__(16) float s_in[2][CI][18][36];
    __shared__ __align__(16) float s_w[2][4][CI][16];

    const int tY   = blockIdx.x / tilesX;
    const int tX   = blockIdx.x - tY * tilesX;
    const int oc0  = blockIdx.y * 4;
    const int n    = blockIdx.z;
    const int tid  = threadIdx.x;
    const int ty   = tid >> 3, tx = tid & 7;
    const int iR0  = tY * 16;
    const int iC0  = tX * 32;
    const int Hout = 2 * Hin, Wout = 2 * Win;

    const float* inN = in + (size_t)n * Cin * Hin * Win;
    const int nCh = Cin / CI;

    auto prefetch = [&](int ch, int st) {
        const float* gi = inN + (size_t)ch * CI * Hin * Win;
        for (int k = tid; k < CI * 18 * 8; k += 128) {
            int ci = k / 144;
            int rem = k - ci * 144;
            int r = rem >> 3, j = rem & 7;
            int gr = iR0 - 1 + r;
            bool p = (unsigned)gr < (unsigned)Hin;
            int grc = p ? gr : 0;
            cp16(smem_u32(&s_in[st][ci][r][4 * j]), gi + (size_t)ci * Hin * Win + (size_t)grc * Win + iC0 + 4 * j, p);
        }
        for (int k = tid; k < CI * 18; k += 128) {
            int ci = k / 18, r = k - ci * 18;
            int gr = iR0 - 1 + r;
            bool rok = (unsigned)gr < (unsigned)Hin;
            int grc = rok ? gr : 0;
            const float* rowp = gi + (size_t)ci * Hin * Win + (size_t)grc * Win;
            cp4(smem_u32(&s_in[st][ci][r][34]), rowp + iC0 - 1, rok && iC0 > 0);
            cp4(smem_u32(&s_in[st][ci][r][32]), rowp + iC0 + 32, rok && (iC0 + 32 < Win));
        }
        if (tid < 4 * CI * 4) {
            int pair = tid >> 2, seg = tid & 3;
            int oc = pair / CI, ci = pair - oc * CI;
            bool p = (oc0 + oc) < Cout;
            const float* gw = wgt + ((size_t)(oc0 + oc) * Cin + ch * CI + ci) * 16 + seg * 4;
            cp16(smem_u32(&s_w[st][oc][ci][seg * 4]), p ? gw : wgt, p);
        }
    };

    float acc[4][2][8];
#pragma unroll
    for (int o = 0; o < 4; o++)
#pragma unroll
        for (int a = 0; a < 2; a++)
#pragma unroll
            for (int u = 0; u < 8; u++) acc[o][a][u] = 0.f;

    prefetch(0, 0);
    cp_commit();

    const int lidx = (tx == 0) ? 34 : (4 * tx - 1);

    for (int ch = 0; ch < nCh; ch++) {
        int st = ch & 1;
        if (ch + 1 < nCh) { prefetch(ch + 1, st ^ 1); cp_commit(); cp_wait1(); }
        else              { cp_wait0(); }
        __syncthreads();
#pragma unroll 1
        for (int ci = 0; ci < CI; ci++) {
            float rin[3][6];
#pragma unroll
            for (int r = 0; r < 3; r++) {
                int rr = ty + r;
                rin[r][0] = s_in[st][ci][rr][lidx];
                float4 m = *(const float4*)&s_in[st][ci][rr][4 * tx];
                rin[r][1] = m.x; rin[r][2] = m.y; rin[r][3] = m.z; rin[r][4] = m.w;
                rin[r][5] = s_in[st][ci][rr][4 * tx + 4];
            }
#pragma unroll
            for (int oc = 0; oc < 4; oc++) {
                float wk[16];
#pragma unroll
                for (int s4 = 0; s4 < 4; s4++) {
                    float4 w = *(const float4*)&s_w[st][oc][ci][4 * s4];
                    wk[4 * s4] = w.x; wk[4 * s4 + 1] = w.y; wk[4 * s4 + 2] = w.z; wk[4 * s4 + 3] = w.w;
                }
#pragma unroll
                for (int jj = 0; jj < 4; jj++) {
#pragma unroll
                    for (int a = 0; a < 2; a++) {
                        const int rlo = a, rhi = a + 1;
                        const int khlo = a, khhi = a + 2;
#pragma unroll
                        for (int b = 0; b < 2; b++) {
                            const int clo = jj + b, chi = jj + 1 + b;
                            const int kwlo = b, kwhi = b + 2;
                            float v = acc[oc][a][2 * jj + b];
                            v = fmaf(rin[rlo][clo], wk[khlo * 4 + kwlo], v);
                            v = fmaf(rin[rlo][chi], wk[khlo * 4 + kwhi], v);
                            v = fmaf(rin[rhi][clo], wk[khhi * 4 + kwlo], v);
                            v = fmaf(rin[rhi][chi], wk[khhi * 4 + kwhi], v);
                            acc[oc][a][2 * jj + b] = v;
                        }
                    }
                }
            }
        }
        __syncthreads();
    }

#pragma unroll
    for (int oc = 0; oc < 4; oc++) {
        int ocg = oc0 + oc;
        if (ocg >= Cout) break;
        float bv = bias[ocg];
#pragma unroll
        for (int a = 0; a < 2; a++) {
            int p = 2 * (iR0 + ty) + a;
            int q = 2 * (iC0 + 4 * tx);
            size_t o = (((size_t)n * Cout + ocg) * Hout + p) * Wout + q;
            float4 v0, v1;
            v0.x = acc[oc][a][0] + bv; v0.y = acc[oc][a][1] + bv;
            v0.z = acc[oc][a][2] + bv; v0.w = acc[oc][a][3] + bv;
            v1.x = acc[oc][a][4] + bv; v1.y = acc[oc][a][5] + bv;
            v1.z = acc[oc][a][6] + bv; v1.w = acc[oc][a][7] + bv;
            if (RELU_OUT) {
                v0.x = fmaxf(v0.x, 0.f); v0.y = fmaxf(v0.y, 0.f);
                v0.z = fmaxf(v0.z, 0.f); v0.w = fmaxf(v0.w, 0.f);
                v1.x = fmaxf(v1.x, 0.f); v1.y = fmaxf(v1.y, 0.f);
                v1.z = fmaxf(v1.z, 0.f); v1.w = fmaxf(v1.w, 0.f);
            }
            *(float4*)&out[o] = v0;
            *(float4*)&out[o + 4] = v1;
        }
    }
}

// ======================= generic direct conv (e1 and 1x1 convs) =======================
template<int K, int S, int CI, int OCPT, bool RELU_IN, bool RELU_OUT, bool ADD, bool BN>
__global__ __launch_bounds__(128)
void conv_generic(const float* __restrict__ in, const float* __restrict__ wgt,
                  const float* __restrict__ bias, float* __restrict__ out,
                  int Cin, int Cout, int Hin, int Win, int Hout, int Wout, int tilesX,
                  const float* __restrict__ bnsc, const float* __restrict__ bnsh)
{
    constexpr int P   = (K == 1) ? 0 : 1;
    constexpr int IT  = 31 * S + K;
    constexpr int ITS = IT + 1;
    constexpr int KK  = K * K;
    constexpr int RR  = S + K;
    constexpr int CC  = 3 * S + K;

    __shared__ float s_in[CI][IT][ITS];
    __shared__ float s_w[OCPT][CI][KK];

    const int n   = blockIdx.z;
    const int oc0 = blockIdx.y * OCPT;
    const int tY  = blockIdx.x / tilesX;
    const int tX  = blockIdx.x - tY * tilesX;
    const int oR0 = tY * 32, oC0 = tX * 32;
    const int iR0 = oR0 * S - P, iC0 = oC0 * S - P;
    const int tid = threadIdx.x;
    const int ty  = tid >> 3, tx = tid & 7;

    float acc[OCPT][2][4];
#pragma unroll
    for (int o = 0; o < OCPT; o++)
#pragma unroll
        for (int r = 0; r < 2; r++)
#pragma unroll
            for (int c = 0; c < 4; c++) acc[o][r][c] = 0.f;

    const float* inN = in + (size_t)n * Cin * Hin * Win;

    for (int ic0 = 0; ic0 < Cin; ic0 += CI) {
        __syncthreads();
        for (int idx = tid; idx < CI * IT * IT; idx += 128) {
            int ci  = idx / (IT * IT);
            int rem = idx - ci * (IT * IT);
            int r   = rem / IT;
            int c   = rem - r * IT;
            int gr = iR0 + r, gc = iC0 + c;
            float v = 0.f;
            if ((unsigned)gr < (unsigned)Hin && (unsigned)gc < (unsigned)Win) {
                v = inN[((size_t)(ic0 + ci) * Hin + gr) * Win + gc];
                if (RELU_IN) v = fmaxf(v, 0.f);
            }
            s_in[ci][r][c] = v;
        }
        for (int idx = tid; idx < OCPT * CI * KK; idx += 128) {
            int oc  = idx / (CI * KK);
            int rem = idx - oc * (CI * KK);
            int ci  = rem / KK;
            int k   = rem - ci * KK;
            float wv = 0.f;
            if (oc0 + oc < Cout) wv = wgt[((size_t)(oc0 + oc) * Cin + ic0 + ci) * KK + k];
            s_w[oc][ci][k] = wv;
        }
        __syncthreads();
#pragma unroll 1
        for (int ci = 0; ci < CI; ci++) {
            float rin[RR][CC];
#pragma unroll
            for (int r = 0; r < RR; r++)
#pragma unroll
                for (int c = 0; c < CC; c++)
                    rin[r][c] = s_in[ci][2 * ty * S + r][4 * tx * S + c];
#pragma unroll
            for (int oc = 0; oc < OCPT; oc++) {
                float wk[KK];
#pragma unroll
                for (int k = 0; k < KK; k++) wk[k] = s_w[oc][ci][k];
#pragma unroll
                for (int ry = 0; ry < 2; ry++)
#pragma unroll
                    for (int cx = 0; cx < 4; cx++) {
                        float a = acc[oc][ry][cx];
#pragma unroll
                        for (int kh = 0; kh < K; kh++)
#pragma unroll
                            for (int kw = 0; kw < K; kw++)
                                a = fmaf(rin[ry * S + kh][cx * S + kw], wk[kh * K + kw], a);
                        acc[oc][ry][cx] = a;
                    }
            }
        }
    }
#pragma unroll
    for (int oc = 0; oc < OCPT; oc++) {
        int ocg = oc0 + oc;
        if (ocg >= Cout) break;
        float bv = bias[ocg];
        float sc = 1.f, sh = 0.f;
        if (BN) { sc = bnsc[ocg]; sh = bnsh[ocg]; }
#pragma unroll
        for (int ry = 0; ry < 2; ry++) {
            int r = oR0 + 2 * ty + ry;
#pragma unroll
            for (int cx = 0; cx < 4; cx++) {
                int c = oC0 + 4 * tx + cx;
                size_t o = (((size_t)n * Cout + ocg) * Hout + r) * Wout + c;
                float v = acc[oc][ry][cx] + bv;
                if (BN) v = v * sc + sh;
                if (ADD) v += out[o];
                if (RELU_OUT) v = fmaxf(v, 0.f);
                out[o] = v;
            }
        }
    }
}

// ======================= BN fold =======================
__global__ void bn_prep(const float* __restrict__ g, const float* __restrict__ b,
                        const float* __restrict__ m, const float* __restrict__ v,
                        float* __restrict__ sc, float* __restrict__ sh)
{
    int c = threadIdx.x;
    if (c < 128) {
        float s = g[c] / sqrtf(v[c] + 1e-5f);
        sc[c] = s;
        sh[c] = b[c] - m[c] * s;
    }
}

// ======================= VQ =======================
__global__ void vq_cbnorm(const float* __restrict__ cb, float* __restrict__ cbn)
{
    int k = blockIdx.x * blockDim.x + threadIdx.x;
    if (k >= 512) return;
    float s = 0.f;
    for (int c = 0; c < 128; c++) { float v = cb[k * 128 + c]; s = fmaf(v, v, s); }
    cbn[k] = s;
}

__global__ void vq_init(float* __restrict__ hist, float* __restrict__ commit)
{
    int t = threadIdx.x;
    if (t < 512) hist[t] = 0.f;
    if (t == 0) *commit = 0.f;
}

__global__ __launch_bounds__(256)
void vq_gemm(const float* __restrict__ z, const float* __restrict__ cb, float* __restrict__ scores)
{
    __shared__ float sA[16][128];
    __shared__ float sB[16][65];
    const int mt = blockIdx.x;
    const int kt = blockIdx.y;
    const int n  = mt >> 3;
    const int s0 = (mt & 7) << 7;
    const int m0 = mt << 7;
    const int k0 = kt << 6;
    const int tid = threadIdx.x;
    const int tr = tid >> 4, tc = tid & 15;

    float acc[8][4];
#pragma unroll
    for (int i = 0; i < 8; i++)
#pragma unroll
        for (int j = 0; j < 4; j++) acc[i][j] = 0.f;

    const float* zb = z + (size_t)n * 131072 + s0;

    for (int c0 = 0; c0 < 128; c0 += 16) {
        __syncthreads();
#pragma unroll
        for (int i = 0; i < 8; i++) {
            int idx = tid + i * 256;
            int cl = idx >> 7, ml = idx & 127;
            sA[cl][ml] = zb[(size_t)(c0 + cl) * 1024 + ml];
        }
#pragma unroll
        for (int i = 0; i < 4; i++) {
            int idx = tid + i * 256;
            int kl = idx >> 4, cl = idx & 15;
            sB[cl][kl] = cb[(size_t)(k0 + kl) * 128 + c0 + cl];
        }
        __syncthreads();
#pragma unroll
        for (int kk = 0; kk < 16; kk++) {
            float a[8], b[4];
#pragma unroll
            for (int i = 0; i < 8; i++) a[i] = sA[kk][i * 16 + tr];
#pragma unroll
            for (int j = 0; j < 4; j++) b[j] = sB[kk][j * 16 + tc];
#pragma unroll
            for (int i = 0; i < 8; i++)
#pragma unroll
                for (int j = 0; j < 4; j++)
                    acc[i][j] = fmaf(a[i], b[j], acc[i][j]);
        }
    }
#pragma unroll
    for (int i = 0; i < 8; i++)
#pragma unroll
        for (int j = 0; j < 4; j++)
            scores[(size_t)(m0 + i * 16 + tr) * 512 + k0 + j * 16 + tc] = acc[i][j];
}

__global__ __launch_bounds__(256)
void vq_argmin(const float* __restrict__ scores, const float* __restrict__ cbn, int* __restrict__ idxo)
{
    int gw = (blockIdx.x * blockDim.x + threadIdx.x) >> 5;
    int lane = threadIdx.x & 31;
    if (gw >= 16384) return;
    const float* row = scores + (size_t)gw * 512;
    float best = 3.4e38f;
    int bi = 0;
    for (int k = lane; k < 512; k += 32) {
        float v = cbn[k] - 2.f * row[k];
        if (v < best) { best = v; bi = k; }
    }
#pragma unroll
    for (int off = 16; off; off >>= 1) {
        float ob = __shfl_down_sync(0xFFFFFFFFu, best, off);
        int   oi = __shfl_down_sync(0xFFFFFFFFu, bi, off);
        if (ob < best || (ob == best && oi < bi)) { best = ob; bi = oi; }
    }
    if (lane == 0) idxo[gw] = bi;
}

__global__ __launch_bounds__(256)
void vq_gather(const float* __restrict__ z, const float* __restrict__ cb,
               const int* __restrict__ idx, float* __restrict__ zq,
               float* __restrict__ hist, float* __restrict__ commit)
{
    int m = blockIdx.x * 256 + threadIdx.x;
    int n = m >> 10, s = m & 1023;
    int k = idx[m];
    atomicAdd(&hist[k], 1.0f);
    const float* zb  = z  + (size_t)n * 131072 + s;
    float*       qb  = zq + (size_t)n * 131072 + s;
    const float* cbk = cb + (size_t)k * 128;
    float sum = 0.f;
    for (int c = 0; c < 128; c++) {
        float q  = __ldg(&cbk[c]);
        float zv = zb[(size_t)c * 1024];
        qb[(size_t)c * 1024] = q;
        float d = zv - q;
        sum = fmaf(d, d, sum);
    }
    __shared__ float red[256];
    red[threadIdx.x] = sum;
    __syncthreads();
    for (int o = 128; o; o >>= 1) {
        if (threadIdx.x < o) red[threadIdx.x] += red[threadIdx.x + o];
        __syncthreads();
    }
    if (threadIdx.x == 0) atomicAdd(commit, red[0]);
}

__global__ void vq_finalize(const float* __restrict__ hist, const float* __restrict__ commit,
                            float* __restrict__ out2)
{
    __shared__ float red[512];
    int k = threadIdx.x;
    float p = hist[k] * (1.0f / 16384.0f);
    red[k] = p * logf(p + 1e-10f);
    __syncthreads();
    for (int o = 256; o; o >>= 1) {
        if (k < o) red[k] += red[k + o];
        __syncthreads();
    }
    if (k == 0) {
        out2[0] = 0.25f * (*commit) / (16384.0f * 128.0f);
        out2[1] = expf(-red[0]);
    }
}

// ======================= launch =======================
extern "C" void kernel_launch(void* const* d_in, const int* in_sizes, int n_in,
                              void* d_out, int out_size)
{
    (void)in_sizes; (void)n_in;
    const float* x        = (const float*)d_in[0];
    const float* e1_w     = (const float*)d_in[1];
    const float* e1_b     = (const float*)d_in[2];
    const float* e2_w     = (const float*)d_in[3];
    const float* e2_b     = (const float*)d_in[4];
    const float* e3_w     = (const float*)d_in[5];
    const float* e3_b     = (const float*)d_in[6];
    const float* enc_rw1  = (const float*)d_in[7];
    const float* enc_rb1  = (const float*)d_in[8];
    const float* enc_rw2  = (const float*)d_in[9];
    const float* enc_rb2  = (const float*)d_in[10];
    const float* lat_w    = (const float*)d_in[11];
    const float* lat_b    = (const float*)d_in[12];
    const float* bn_gamma = (const float*)d_in[13];
    const float* bn_beta  = (const float*)d_in[14];
    const float* bn_mean  = (const float*)d_in[15];
    const float* bn_var   = (const float*)d_in[16];
    const float* codebook = (const float*)d_in[17];
    const float* din_w    = (const float*)d_in[18];
    const float* din_b    = (const float*)d_in[19];
    const float* dec_rw1  = (const float*)d_in[20];
    const float* dec_rb1  = (const float*)d_in[21];
    const float* dec_rw2  = (const float*)d_in[22];
    const float* dec_rb2  = (const float*)d_in[23];
    const float* d1_w     = (const float*)d_in[24];
    const float* d1_b     = (const float*)d_in[25];
    const float* d2_w     = (const float*)d_in[26];
    const float* d2_b     = (const float*)d_in[27];
    const float* d3_w     = (const float*)d_in[28];
    const float* d3_b     = (const float*)d_in[29];

    void* p;
    float *a, *b, *c, *t, *z, *zq, *d, *scores, *cbn, *hist, *commit, *bnsc, *bnsh;
    __nv_bfloat16 *nhHi, *nhLo, *wHi, *wLo, *eHi, *eLo, *wd1Hi, *wd1Lo, *wd2Hi, *wd2Lo;
    int* idx;
    cudaGetSymbolAddress(&p, g_a);      a      = (float*)p;
    cudaGetSymbolAddress(&p, g_b);      b      = (float*)p;
    cudaGetSymbolAddress(&p, g_c);      c      = (float*)p;
    cudaGetSymbolAddress(&p, g_t);      t      = (float*)p;
    cudaGetSymbolAddress(&p, g_z);      z      = (float*)p;
    cudaGetSymbolAddress(&p, g_zq);     zq     = (float*)p;
    cudaGetSymbolAddress(&p, g_d);      d      = (float*)p;
    cudaGetSymbolAddress(&p, g_scores); scores = (float*)p;
    cudaGetSymbolAddress(&p, g_idx);    idx    = (int*)p;
    cudaGetSymbolAddress(&p, g_cbnorm); cbn    = (float*)p;
    cudaGetSymbolAddress(&p, g_hist);   hist   = (float*)p;
    cudaGetSymbolAddress(&p, g_commit); commit = (float*)p;
    cudaGetSymbolAddress(&p, g_bnscale); bnsc  = (float*)p;
    cudaGetSymbolAddress(&p, g_bnshift); bnsh  = (float*)p;
    cudaGetSymbolAddress(&p, g_nh_hi);  nhHi   = (__nv_bfloat16*)p;
    cudaGetSymbolAddress(&p, g_nh_lo);  nhLo   = (__nv_bfloat16*)p;
    cudaGetSymbolAddress(&p, g_w_hi);   wHi    = (__nv_bfloat16*)p;
    cudaGetSymbolAddress(&p, g_w_lo);   wLo    = (__nv_bfloat16*)p;
    cudaGetSymbolAddress(&p, g_e_hi);   eHi    = (__nv_bfloat16*)p;
    cudaGetSymbolAddress(&p, g_e_lo);   eLo    = (__nv_bfloat16*)p;
    cudaGetSymbolAddress(&p, g_wd1_hi); wd1Hi  = (__nv_bfloat16*)p;
    cudaGetSymbolAddress(&p, g_wd1_lo); wd1Lo  = (__nv_bfloat16*)p;
    cudaGetSymbolAddress(&p, g_wd2_hi); wd2Hi  = (__nv_bfloat16*)p;
    cudaGetSymbolAddress(&p, g_wd2_lo); wd2Lo  = (__nv_bfloat16*)p;

    float* out = (float*)d_out;

    cudaFuncSetAttribute(gemm_conv3<false>, cudaFuncAttributeMaxDynamicSharedMemorySize, GSM_TOTAL);
    cudaFuncSetAttribute(gemm_conv3<true>,  cudaFuncAttributeMaxDynamicSharedMemorySize, GSM_TOTAL);
    cudaFuncSetAttribute(gemm_deconv<32, 256, true>,  cudaFuncAttributeMaxDynamicSharedMemorySize, GSM_TOTAL);
    cudaFuncSetAttribute(gemm_deconv<64, 128, false>, cudaFuncAttributeMaxDynamicSharedMemorySize, GSM_TOTAL);

    // ---- prep ----
    zero_halo<<<16 * 132, 256>>>(nhHi, nhLo);
    zero_halo66<<<16 * 260, 256>>>(eHi, eLo);
    prep_wsplit<<<(8 * 9 * 65536 + 255) / 256, 256>>>(dec_rw1, dec_rw2, wHi, wLo);
    prep_wsplit_dc<<<4096, 256>>>(d1_w, wd1Hi, wd1Lo, 256);
    prep_wsplit_dc<<<2048, 256>>>(d2_w, wd2Hi, wd2Lo, 128);

    // ---- encoder: three stride-2 4x4 convs, relu ----
    conv_generic<4, 2, 1, 4, false, true, false, false>
        <<<dim3(16, 32, 16), 128>>>(x, e1_w, e1_b, a, 3, 128, 256, 256, 128, 128, 4, nullptr, nullptr);
    conv4s2_pipe<<<dim3(8, 16, 16), 64>>>(a, e2_w, e2_b, b, 128, 128, 128, 128, 2);
    conv4s2_pipe<<<dim3(2, 32, 16), 64>>>(b, e3_w, e3_b, c, 128, 256, 64, 64, 1);

    // ---- encoder resblocks (exact fp32 SIMT; relu fused into conv1 output) ----
    for (int i = 0; i < 4; i++) {
        const float* w1 = enc_rw1 + (size_t)i * 256 * 256 * 9;
        const float* b1 = enc_rb1 + (size_t)i * 256;
        const float* w2 = enc_rw2 + (size_t)i * 256 * 256 * 9;
        const float* b2 = enc_rb2 + (size_t)i * 256;
        if (i == 0)
            conv3_pipe<false, true, false><<<dim3(2, 32, 16), 64>>>(c, w1, b1, t, 256, 256);
        else
            conv3_pipe<true, true, false><<<dim3(2, 32, 16), 64>>>(c, w1, b1, t, 256, 256);
        conv3_pipe<false, false, true><<<dim3(2, 32, 16), 64>>>(t, w2, b2, c, 256, 256);
    }

    // ---- latent 1x1 conv + folded BN ----
    bn_prep<<<1, 128>>>(bn_gamma, bn_beta, bn_mean, bn_var, bnsc, bnsh);
    conv_generic<1, 1, 8, 8, false, false, false, true>
        <<<dim3(1, 16, 16), 128>>>(c, lat_w, lat_b, z, 256, 128, 32, 32, 32, 32, 1, bnsc, bnsh);

    // ---- VQ ----
    vq_cbnorm<<<2, 256>>>(codebook, cbn);
    vq_init<<<1, 512>>>(hist, commit);
    vq_gemm<<<dim3(128, 8), 256>>>(z, codebook, scores);
    vq_argmin<<<2048, 256>>>(scores, cbn, idx);
    vq_gather<<<64, 256>>>(z, codebook, idx, zq, hist, commit);

    // ---- decoder 1x1 ----
    conv_generic<1, 1, 8, 8, false, false, false, false>
        <<<dim3(1, 32, 16), 128>>>(zq, din_w, din_b, d, 128, 256, 32, 32, 32, 32, 1, nullptr, nullptr);

    const size_t WSET = (size_t)9 * 65536;
    // ---- decoder resblocks (bf16-split tensor-core GEMM) ----
    for (int i = 0; i < 4; i++) {
        split_nhwc<true><<<512, 256>>>(d, nhHi, nhLo);
        gemm_conv3<false><<<128, 512, GSM_TOTAL>>>(nhHi, nhLo, wHi + (size_t)i * WSET, wLo + (size_t)i * WSET,
                                                   dec_rb1 + (size_t)i * 256, t);
        split_nhwc<true><<<512, 256>>>(t, nhHi, nhLo);
        gemm_conv3<true><<<128, 512, GSM_TOTAL>>>(nhHi, nhLo, wHi + (size_t)(4 + i) * WSET, wLo + (size_t)(4 + i) * WSET,
                                                  dec_rb2 + (size_t)i * 256, d);
    }

    // ---- decoder deconvs: d1, d2 as bf16-split GEMMs, d3 fp32 ----
    split_nhwc<false><<<512, 256>>>(d, nhHi, nhLo);
    gemm_deconv<32, 256, true><<<dim3(128, 4), 512, GSM_TOTAL>>>(
        nhHi, nhLo, wd1Hi, wd1Lo, d1_b, eHi, eLo, nullptr);
    gemm_deconv<64, 128, false><<<dim3(256, 4), 512, GSM_TOTAL>>>(
        eHi, eLo, wd2Hi, wd2Lo, d2_b, nullptr, nullptr, a);
    deconv_pipe<false><<<dim3(32, 2, 16), 128>>>(a, d3_w, d3_b, out, 128, 5, 128, 128, 4);

    // ---- scalars (vq_loss, perplexity) appended after recon ----
    if (out_size >= 5242882) {
        vq_finalize<<<1, 512>>>(hist, commit, out + 5242880);
    }
}